// round 9
// baseline (speedup 1.0000x reference)
#include <cuda_runtime.h>
#include <math.h>
#include <stdint.h>

// ---------------------------------------------------------------------------
// Scratch (__device__ globals; no allocation allowed)
// ---------------------------------------------------------------------------
__device__ float g_pos[32 * 1024];              // [32 ch][1024], fp32
__device__ float g_x0[32 * 160 * 1024];         // tf32 [B][160][N]  (x|pos)
__device__ float g_kc[32 * 128 * 1024];         // tf32 k
__device__ float g_vc[32 * 128 * 1024];         // tf32 v
__device__ float g_q [32 * 128 * 1024];         // tf32 q
__device__ float g_Wq [128 * 160];              // tf32 weights
__device__ float g_Wfk[128 * 288];
__device__ float g_Wck[128 * 288];
__device__ float g_Wfv[128 * 288];
__device__ float g_Wcv[128 * 288];
// Split-K attention partials: [2 splits][32 b][128 v][1024 n] + stats
__device__ float g_po[2 * 32 * 128 * 1024];     // 33.5 MB, unnormalized O
__device__ float g_pm[2 * 32 * 1024];           // row max
__device__ float g_pl[2 * 32 * 1024];           // row sum

// ---------------------------------------------------------------------------
// Helpers
// ---------------------------------------------------------------------------
__device__ __forceinline__ uint32_t f2tf(float x) {
    uint32_t u;
    asm("cvt.rna.tf32.f32 %0, %1;" : "=r"(u) : "f"(x));
    return u;
}
__device__ __forceinline__ float f2tff(float x) { return __uint_as_float(f2tf(x)); }

__device__ __forceinline__ void mma_tf32(
    float& d0, float& d1, float& d2, float& d3,
    uint32_t a0, uint32_t a1, uint32_t a2, uint32_t a3,
    uint32_t b0, uint32_t b1)
{
    asm volatile(
        "mma.sync.aligned.m16n8k8.row.col.f32.tf32.tf32.f32 "
        "{%0,%1,%2,%3}, {%4,%5,%6,%7}, {%8,%9}, {%0,%1,%2,%3};"
        : "+f"(d0), "+f"(d1), "+f"(d2), "+f"(d3)
        : "r"(a0), "r"(a1), "r"(a2), "r"(a3), "r"(b0), "r"(b1));
}

__device__ __forceinline__ void cpa16(uint32_t dst, const void* src) {
    asm volatile("cp.async.ca.shared.global [%0], [%1], 16;" :: "r"(dst), "l"(src));
}
#define CP_COMMIT() asm volatile("cp.async.commit_group;" ::: "memory")

// ---------------------------------------------------------------------------
// Positional embedding (faithful to numpy .view reinterpret)
// ---------------------------------------------------------------------------
__global__ void pos_kernel() {
    int idx = blockIdx.x * blockDim.x + threadIdx.x;
    if (idx >= 32 * 1024) return;
    int c = idx >> 10, n = idx & 1023;
    int y = n >> 5, x = n & 31;
    int i = (c < 16) ? (c * 32 + y) : ((c - 16) * 32 + x);
    int p = i >> 4, j = i & 15;
    float r = 0.0f;
    if (p != 0) {
        double denom = pow(10000.0, (double)(2 * (j >> 1)) / 16.0);
        double val = (double)p / denom;
        r = (j & 1) ? (float)cos(val) : (float)sin(val);
    }
    g_pos[idx] = r;
}

// ---------------------------------------------------------------------------
// Pack: tf32-round inputs AND weights into scratch (one launch)
// ---------------------------------------------------------------------------
__device__ __forceinline__ float4 tf4(float4 s) {
    s.x = f2tff(s.x); s.y = f2tff(s.y); s.z = f2tff(s.z); s.w = f2tff(s.w);
    return s;
}

#define PACK_NX0 (32 * 160 * 256)
#define PACK_NKV (32 * 128 * 256)
#define PACK_DATA (PACK_NX0 + 2 * PACK_NKV)
#define PACK_TOTAL (PACK_DATA + 128 * 288)

__global__ void pack_kernel(const float* __restrict__ x,
                            const float* __restrict__ k,
                            const float* __restrict__ v,
                            const float* __restrict__ Wq,
                            const float* __restrict__ Wfk, const float* __restrict__ Wck,
                            const float* __restrict__ Wfv, const float* __restrict__ Wcv)
{
    int i = blockIdx.x * blockDim.x + threadIdx.x;
    if (i < PACK_NX0) {
        int n4 = i & 255;
        int cb = i >> 8;
        int c = cb % 160, b = cb / 160;
        float4 s;
        if (c < 128)
            s = ((const float4*)x)[(size_t)(b * 128 + c) * 256 + n4];
        else
            s = ((const float4*)g_pos)[(c - 128) * 256 + n4];
        ((float4*)g_x0)[i] = tf4(s);
    } else if (i < PACK_NX0 + PACK_NKV) {
        int j = i - PACK_NX0;
        ((float4*)g_kc)[j] = tf4(((const float4*)k)[j]);
    } else if (i < PACK_DATA) {
        int j = i - PACK_NX0 - PACK_NKV;
        ((float4*)g_vc)[j] = tf4(((const float4*)v)[j]);
    } else {
        int j = i - PACK_DATA;                 // 0 .. 128*288-1
        if (j < 128 * 160) g_Wq[j] = f2tff(Wq[j]);
        g_Wfk[j] = f2tff(Wfk[j]);
        g_Wck[j] = f2tff(Wck[j]);
        g_Wfv[j] = f2tff(Wfv[j]);
        g_Wcv[j] = f2tff(Wcv[j]);
    }
}

// ---------------------------------------------------------------------------
// q kernel: q = tf32(relu(Wq@x0+bq)), Cin=160, 5 k-steps (extracted; must
// precede the mega kernel because attention reads g_q).
// ---------------------------------------------------------------------------
#define GSA 36          // A smem row stride (words); 36 % 32 == 4
#define GSB 136         // B smem row stride; 136 % 32 == 8
#define GBUF 8960       // floats per gated pipeline buffer (2*64*GSA + 32*GSB)
#define QBUF 6656       // floats per q pipeline buffer (64*GSA + 32*GSB)
#define QSMEM_BYTES (2 * QBUF * 4)

__global__ __launch_bounds__(256, 2) void q_kernel(const float* __restrict__ bq)
{
    extern __shared__ float sm[];
    const int b = blockIdx.z, r0 = blockIdx.y * 64, n0 = blockIdx.x * 128;
    const int t = threadIdx.x, w = t >> 5, lane = t & 31;
    const int lr = lane >> 2, lc = lane & 3;
    const int wm = (w >> 2) * 32;
    const int wn = (w & 3) * 32;
    const uint32_t sbase = (uint32_t)__cvta_generic_to_shared(sm);

    float acc[2][4][4];
    #pragma unroll
    for (int mf = 0; mf < 2; mf++) {
        int rA = r0 + wm + mf * 16 + lr;
        float b0 = bq[rA], b1 = bq[rA + 8];
        #pragma unroll
        for (int nf = 0; nf < 4; nf++) {
            acc[mf][nf][0] = b0; acc[mf][nf][1] = b0;
            acc[mf][nf][2] = b1; acc[mf][nf][3] = b1;
        }
    }

    auto issue = [&](int it, int buf) {
        const int k0 = it * 32;
        const uint32_t base = sbase + buf * (QBUF * 4);
        #pragma unroll
        for (int h = 0; h < 2; h++) {
            int a = t + 256 * h;
            int r = a >> 3, c4 = a & 7;
            cpa16(base + (r * GSA + c4 * 4) * 4,
                  g_Wq + (size_t)(r0 + r) * 160 + k0 + c4 * 4);
        }
        #pragma unroll
        for (int h = 0; h < 4; h++) {
            int bi = t + 256 * h;
            int r = bi >> 5, c4 = bi & 31;
            cpa16(base + (2304 + r * GSB + c4 * 4) * 4,
                  g_x0 + ((size_t)b * 160 + k0 + r) * 1024 + n0 + c4 * 4);
        }
        CP_COMMIT();
    };

    issue(0, 0);
    #pragma unroll 1
    for (int it = 0; it < 5; it++) {
        if (it < 4) {
            issue(it + 1, (it + 1) & 1);
            asm volatile("cp.async.wait_group 1;" ::: "memory");
        } else {
            asm volatile("cp.async.wait_group 0;" ::: "memory");
        }
        __syncthreads();

        const float* As = sm + (it & 1) * QBUF;
        const float* Bs = As + 2304;

        #pragma unroll
        for (int kf = 0; kf < 4; kf++) {
            int kk = kf * 8;
            uint32_t aa[2][4], bb[4][2];
            #pragma unroll
            for (int mf = 0; mf < 2; mf++) {
                int base = (wm + mf * 16 + lr) * GSA + kk + lc;
                aa[mf][0] = __float_as_uint(As[base]);
                aa[mf][1] = __float_as_uint(As[base + 8 * GSA]);
                aa[mf][2] = __float_as_uint(As[base + 4]);
                aa[mf][3] = __float_as_uint(As[base + 8 * GSA + 4]);
            }
            #pragma unroll
            for (int nf = 0; nf < 4; nf++) {
                int base = (kk + lc) * GSB + wn + nf * 8 + lr;
                bb[nf][0] = __float_as_uint(Bs[base]);
                bb[nf][1] = __float_as_uint(Bs[base + 4 * GSB]);
            }
            #pragma unroll
            for (int mf = 0; mf < 2; mf++)
                #pragma unroll
                for (int nf = 0; nf < 4; nf++)
                    mma_tf32(acc[mf][nf][0], acc[mf][nf][1], acc[mf][nf][2], acc[mf][nf][3],
                             aa[mf][0], aa[mf][1], aa[mf][2], aa[mf][3], bb[nf][0], bb[nf][1]);
        }
        __syncthreads();
    }

    #pragma unroll
    for (int mf = 0; mf < 2; mf++) {
        int rA = r0 + wm + mf * 16 + lr;
        #pragma unroll
        for (int nf = 0; nf < 4; nf++) {
            int n = n0 + wn + nf * 8 + 2 * lc;
            #pragma unroll
            for (int h = 0; h < 2; h++) {
                int row = rA + h * 8;
                #pragma unroll
                for (int j = 0; j < 2; j++) {
                    float val = fmaxf(acc[mf][nf][2 * h + j], 0.0f);
                    g_q[((size_t)(b * 128 + row)) * 1024 + n + j] = f2tff(val);
                }
            }
        }
    }
}

// ---------------------------------------------------------------------------
// MEGA kernel: 1536 CTAs, one uniform smem size (106.5 KB) -> 2 CTAs/SM.
//   i % 3 == 0 : attention split-K CTA (a = i/3, 512 total)
//                a: qt = 7 - (a>>6) [heavy first], b = (a&63)>>1, s = a&1
//                s=0: key tiles [0..qt];  s=1: key tiles [qt+1..2qt+1]
//                writes UNNORMALIZED O + (m, l) partials to g_po/g_pm/g_pl
//   else       : gated highway CTA (g = i - i/3 - 1, 1024 total)
// Mixing both types per SM fills each other's latency bubbles (4 warps/SMSP).
// ---------------------------------------------------------------------------
#define SK  72    // Ks stride: 64 keys + 8 pad
#define SV  68    // Vs stride: 64 keys + 4 pad
#define SP  68    // Ps stride: 64 keys + 4 pad
#define A_OFF_KS 0
#define A_OFF_VS (128 * SK)               // 9216
#define A_OFF_PS (128 * SK + 128 * SV)    // 17920
#define MEGA_SMEM_FLOATS (A_OFF_PS + 128 * SP)   // 26624
#define MEGA_SMEM_BYTES (MEGA_SMEM_FLOATS * 4)   // 106496

__global__ __launch_bounds__(256) void mega_kernel(
    const float* __restrict__ kOrig, const float* __restrict__ vOrig,
    const float* __restrict__ bfk, const float* __restrict__ bck,
    const float* __restrict__ bfv, const float* __restrict__ bcv,
    float* __restrict__ outk, float* __restrict__ outv)
{
    extern __shared__ float sm[];
    const int i = blockIdx.x;
    const int t = threadIdx.x, w = t >> 5, lane = t & 31;
    const int lr = lane >> 2, lc = lane & 3;
    const uint32_t sbase = (uint32_t)__cvta_generic_to_shared(sm);

    if (i % 3 == 0) {
        // ===================== attention split-K body =====================
        const int a = i / 3;
        const int qt = 7 - (a >> 6);
        const int b = (a & 63) >> 1;
        const int s = a & 1;
        const int n0 = qt * 128;
        const int mtLo = s ? (qt + 1) : 0;
        const int mtHi = s ? (2 * qt + 1) : qt;
        const int wq = w * 16;
        const float scale = 0.08838834764831845f;
        float* Ps = sm + A_OFF_PS;

        auto issue_k = [&](int mt) {
            const int m0 = mt * 64;
            const uint32_t kb = sbase + A_OFF_KS * 4;
            #pragma unroll
            for (int h = 0; h < 8; h++) {
                int idx = t + 256 * h;
                int c = idx >> 4, m4 = idx & 15;
                cpa16(kb + (c * SK + m4 * 4) * 4,
                      g_kc + ((size_t)(b * 128 + c)) * 1024 + m0 + m4 * 4);
            }
            CP_COMMIT();
        };
        auto issue_v = [&](int mt) {
            const int m0 = mt * 64;
            const uint32_t vb = sbase + A_OFF_VS * 4;
            #pragma unroll
            for (int h = 0; h < 8; h++) {
                int idx = t + 256 * h;
                int c = idx >> 4, m4 = idx & 15;
                cpa16(vb + (c * SV + m4 * 4) * 4,
                      g_vc + ((size_t)(b * 128 + c)) * 1024 + m0 + m4 * 4);
            }
            CP_COMMIT();
        };

        issue_k(mtLo);
        issue_v(mtLo);

        // Q fragments register-resident (overlaps stage-0 cp.async)
        uint32_t qa[16][4];
        #pragma unroll
        for (int kf = 0; kf < 16; kf++) {
            const float* qp = g_q + ((size_t)(b * 128 + kf * 8 + lc)) * 1024 + n0 + wq + lr;
            qa[kf][0] = __float_as_uint(qp[0]);
            qa[kf][1] = __float_as_uint(qp[8]);
            qa[kf][2] = __float_as_uint(qp[4 * 1024]);
            qa[kf][3] = __float_as_uint(qp[4 * 1024 + 8]);
        }

        float mLo = -1e30f, mHi = -1e30f, lLo = 0.0f, lHi = 0.0f;
        float O[16][4];
        #pragma unroll
        for (int nb = 0; nb < 16; nb++)
            #pragma unroll
            for (int j = 0; j < 4; j++) O[nb][j] = 0.0f;

        const int rowLo = n0 + wq + lr;
        const int rowHi = rowLo + 8;

        #pragma unroll 1
        for (int mt = mtLo; mt <= mtHi; mt++) {
            const int m0 = mt * 64;
            const float* Ks = sm + A_OFF_KS;
            const float* Vs = sm + A_OFF_VS;

            // K(mt) ready (pending {K,V} -> wait<=1 drains K)
            asm volatile("cp.async.wait_group 1;" ::: "memory");
            __syncthreads();

            // ---- S = Q^T K : warp tile 16 x 64 (A from registers) ----
            float S[8][4];
            #pragma unroll
            for (int nb = 0; nb < 8; nb++)
                #pragma unroll
                for (int j = 0; j < 4; j++) S[nb][j] = 0.0f;

            #pragma unroll
            for (int kf = 0; kf < 16; kf++) {
                int kc = kf * 8;
                #pragma unroll
                for (int nb = 0; nb < 8; nb++) {
                    int bbase = (kc + lc) * SK + nb * 8 + lr;
                    uint32_t b0 = __float_as_uint(Ks[bbase]);
                    uint32_t b1 = __float_as_uint(Ks[bbase + 4 * SK]);
                    mma_tf32(S[nb][0], S[nb][1], S[nb][2], S[nb][3],
                             qa[kf][0], qa[kf][1], qa[kf][2], qa[kf][3], b0, b1);
                }
            }
            __syncthreads();                  // all warps done reading Ks
            if (mt < mtHi) issue_k(mt + 1);   // hidden behind softmax + PV

            // ---- In-register online softmax (warp-local) ----
            {
                const bool needMask = (m0 + 63 > n0 + wq);
                float tmLo = -1e30f, tmHi = -1e30f;
                #pragma unroll
                for (int nb = 0; nb < 8; nb++) {
                    int c0 = m0 + nb * 8 + 2 * lc, c1 = c0 + 1;
                    float s0 = S[nb][0] * scale, s1 = S[nb][1] * scale;
                    float s2 = S[nb][2] * scale, s3 = S[nb][3] * scale;
                    if (needMask) {
                        if (c0 > rowLo) s0 = -1e30f;
                        if (c1 > rowLo) s1 = -1e30f;
                        if (c0 > rowHi) s2 = -1e30f;
                        if (c1 > rowHi) s3 = -1e30f;
                    }
                    S[nb][0] = s0; S[nb][1] = s1; S[nb][2] = s2; S[nb][3] = s3;
                    tmLo = fmaxf(tmLo, fmaxf(s0, s1));
                    tmHi = fmaxf(tmHi, fmaxf(s2, s3));
                }
                tmLo = fmaxf(tmLo, __shfl_xor_sync(0xffffffffu, tmLo, 1));
                tmLo = fmaxf(tmLo, __shfl_xor_sync(0xffffffffu, tmLo, 2));
                tmHi = fmaxf(tmHi, __shfl_xor_sync(0xffffffffu, tmHi, 1));
                tmHi = fmaxf(tmHi, __shfl_xor_sync(0xffffffffu, tmHi, 2));
                float nmLo = fmaxf(mLo, tmLo), nmHi = fmaxf(mHi, tmHi);
                float aLo = __expf(mLo - nmLo), aHi = __expf(mHi - nmHi);
                mLo = nmLo; mHi = nmHi;
                float sLoSum = 0.0f, sHiSum = 0.0f;
                #pragma unroll
                for (int nb = 0; nb < 8; nb++) {
                    float p0 = f2tff(__expf(S[nb][0] - nmLo));
                    float p1 = f2tff(__expf(S[nb][1] - nmLo));
                    float p2 = f2tff(__expf(S[nb][2] - nmHi));
                    float p3 = f2tff(__expf(S[nb][3] - nmHi));
                    sLoSum += p0 + p1;
                    sHiSum += p2 + p3;
                    int pb = (wq + lr) * SP + nb * 8 + 2 * lc;
                    *(float2*)&Ps[pb]          = make_float2(p0, p1);
                    *(float2*)&Ps[pb + 8 * SP] = make_float2(p2, p3);
                }
                sLoSum += __shfl_xor_sync(0xffffffffu, sLoSum, 1);
                sLoSum += __shfl_xor_sync(0xffffffffu, sLoSum, 2);
                sHiSum += __shfl_xor_sync(0xffffffffu, sHiSum, 1);
                sHiSum += __shfl_xor_sync(0xffffffffu, sHiSum, 2);
                lLo = lLo * aLo + sLoSum;
                lHi = lHi * aHi + sHiSum;
                #pragma unroll
                for (int nb = 0; nb < 16; nb++) {
                    O[nb][0] *= aLo; O[nb][1] *= aLo;
                    O[nb][2] *= aHi; O[nb][3] *= aHi;
                }
            }
            __syncwarp();

            // V(mt) ready (pending {V, K(mt+1)} -> wait<=1; last iter wait 0)
            if (mt < mtHi) {
                asm volatile("cp.async.wait_group 1;" ::: "memory");
            } else {
                asm volatile("cp.async.wait_group 0;" ::: "memory");
            }
            __syncthreads();

            // ---- O += P @ V^T : warp tile 16 rows x 128 v-channels ----
            #pragma unroll
            for (int kf = 0; kf < 8; kf++) {
                int kc = kf * 8;
                int ab = (wq + lr) * SP + kc + lc;
                uint32_t a0 = __float_as_uint(Ps[ab]);
                uint32_t a1 = __float_as_uint(Ps[ab + 8 * SP]);
                uint32_t a2 = __float_as_uint(Ps[ab + 4]);
                uint32_t a3 = __float_as_uint(Ps[ab + 8 * SP + 4]);
                #pragma unroll
                for (int nb = 0; nb < 16; nb++) {
                    int bb = (nb * 8 + lr) * SV + kc + lc;
                    uint32_t b0 = __float_as_uint(Vs[bb]);
                    uint32_t b1 = __float_as_uint(Vs[bb + 4]);
                    mma_tf32(O[nb][0], O[nb][1], O[nb][2], O[nb][3], a0, a1, a2, a3, b0, b1);
                }
            }
            __syncthreads();                  // all warps done reading Vs
            if (mt < mtHi) issue_v(mt + 1);   // hidden behind next S phase
        }

        // Write unnormalized partials + stats
        float* po = g_po + (size_t)(s * 32 + b) * 128 * 1024;
        #pragma unroll
        for (int nb = 0; nb < 16; nb++) {
            int vc = nb * 8 + 2 * lc;
            po[(size_t)vc * 1024 + rowLo]       = O[nb][0];
            po[(size_t)(vc + 1) * 1024 + rowLo] = O[nb][1];
            po[(size_t)vc * 1024 + rowHi]       = O[nb][2];
            po[(size_t)(vc + 1) * 1024 + rowHi] = O[nb][3];
        }
        if (lc == 0) {
            int sb = (s * 32 + b) * 1024;
            g_pm[sb + rowLo] = mLo; g_pl[sb + rowLo] = lLo;
            g_pm[sb + rowHi] = mHi; g_pl[sb + rowHi] = lHi;
        }
    } else {
        // ===================== gated highway body =====================
        const int g = i - i / 3 - 1;               // 0..1023
        const int n0 = (g & 7) * 128;
        const int r0 = ((g >> 3) & 1) * 64;
        const int z = g >> 4;                      // 0..63
        const int b = z >> 1, which = z & 1;
        const float* Wf   = which ? g_Wfv : g_Wfk;
        const float* Wc   = which ? g_Wcv : g_Wck;
        const float* bfp  = which ? bfv : bfk;
        const float* bcp  = which ? bcv : bck;
        const float* extc = which ? g_vc : g_kc;
        const float* extra = which ? vOrig : kOrig;
        float* out = which ? outv : outk;

        const int wm = (w >> 2) * 32;
        const int wn = (w & 3) * 32;

        float accF[2][4][4], accC[2][4][4];
        #pragma unroll
        for (int mf = 0; mf < 2; mf++) {
            int rA = r0 + wm + mf * 16 + lr;
            float bf0 = bfp[rA], bf1 = bfp[rA + 8];
            float bc0 = bcp[rA], bc1 = bcp[rA + 8];
            #pragma unroll
            for (int nf = 0; nf < 4; nf++) {
                accF[mf][nf][0] = bf0; accF[mf][nf][1] = bf0;
                accF[mf][nf][2] = bf1; accF[mf][nf][3] = bf1;
                accC[mf][nf][0] = bc0; accC[mf][nf][1] = bc0;
                accC[mf][nf][2] = bc1; accC[mf][nf][3] = bc1;
            }
        }

        auto issue = [&](int it, int buf) {
            const int k0 = it * 32;
            const uint32_t base = sbase + buf * (GBUF * 4);
            #pragma unroll
            for (int h = 0; h < 2; h++) {
                int a = t + 256 * h;
                int r = a >> 3, c4 = a & 7;
                cpa16(base + (r * GSA + c4 * 4) * 4,
                      Wf + (size_t)(r0 + r) * 288 + k0 + c4 * 4);
                cpa16(base + (2304 + r * GSA + c4 * 4) * 4,
                      Wc + (size_t)(r0 + r) * 288 + k0 + c4 * 4);
            }
            #pragma unroll
            for (int h = 0; h < 4; h++) {
                int bi = t + 256 * h;
                int r = bi >> 5, c4 = bi & 31;
                int row = k0 + r;
                const float* src = (row < 160)
                    ? (g_x0 + ((size_t)b * 160 + row) * 1024 + n0 + c4 * 4)
                    : (extc + ((size_t)b * 128 + (row - 160)) * 1024 + n0 + c4 * 4);
                cpa16(base + (4608 + r * GSB + c4 * 4) * 4, src);
            }
            CP_COMMIT();
        };

        issue(0, 0);
        #pragma unroll 1
        for (int it = 0; it < 9; it++) {
            if (it < 8) {
                issue(it + 1, (it + 1) & 1);
                asm volatile("cp.async.wait_group 1;" ::: "memory");
            } else {
                asm volatile("cp.async.wait_group 0;" ::: "memory");
            }
            __syncthreads();

            const float* AsF = sm + (it & 1) * GBUF;
            const float* AsC = AsF + 2304;
            const float* Bs  = AsF + 4608;

            #pragma unroll
            for (int kf = 0; kf < 4; kf++) {
                int kk = kf * 8;
                uint32_t aF[2][4], aC[2][4], bb[4][2];
                #pragma unroll
                for (int mf = 0; mf < 2; mf++) {
                    int base = (wm + mf * 16 + lr) * GSA + kk + lc;
                    aF[mf][0] = __float_as_uint(AsF[base]);
                    aF[mf][1] = __float_as_uint(AsF[base + 8 * GSA]);
                    aF[mf][2] = __float_as_uint(AsF[base + 4]);
                    aF[mf][3] = __float_as_uint(AsF[base + 8 * GSA + 4]);
                    aC[mf][0] = __float_as_uint(AsC[base]);
                    aC[mf][1] = __float_as_uint(AsC[base + 8 * GSA]);
                    aC[mf][2] = __float_as_uint(AsC[base + 4]);
                    aC[mf][3] = __float_as_uint(AsC[base + 8 * GSA + 4]);
                }
                #pragma unroll
                for (int nf = 0; nf < 4; nf++) {
                    int base = (kk + lc) * GSB + wn + nf * 8 + lr;
                    bb[nf][0] = __float_as_uint(Bs[base]);
                    bb[nf][1] = __float_as_uint(Bs[base + 4 * GSB]);
                }
                #pragma unroll
                for (int mf = 0; mf < 2; mf++)
                    #pragma unroll
                    for (int nf = 0; nf < 4; nf++) {
                        mma_tf32(accF[mf][nf][0], accF[mf][nf][1], accF[mf][nf][2], accF[mf][nf][3],
                                 aF[mf][0], aF[mf][1], aF[mf][2], aF[mf][3], bb[nf][0], bb[nf][1]);
                        mma_tf32(accC[mf][nf][0], accC[mf][nf][1], accC[mf][nf][2], accC[mf][nf][3],
                                 aC[mf][0], aC[mf][1], aC[mf][2], aC[mf][3], bb[nf][0], bb[nf][1]);
                    }
            }
            __syncthreads();
        }

        #pragma unroll
        for (int mf = 0; mf < 2; mf++) {
            int rA = r0 + wm + mf * 16 + lr;
            #pragma unroll
            for (int nf = 0; nf < 4; nf++) {
                int n = n0 + wn + nf * 8 + 2 * lc;
                #pragma unroll
                for (int h = 0; h < 2; h++) {
                    int row = rA + h * 8;
                    #pragma unroll
                    for (int j = 0; j < 2; j++) {
                        float F  = accF[mf][nf][2 * h + j];
                        float Cc = accC[mf][nf][2 * h + j];
                        float f  = 1.0f / (1.0f + __expf(-F));
                        float cc = fmaxf(Cc, 0.0f);
                        size_t off = ((size_t)(b * 128 + row)) * 1024 + n + j;
                        out[off] = f * extra[off] + cc;
                    }
                }
            }
        }
    }
}

// ---------------------------------------------------------------------------
// Combine split-K partials: out = (O0*e0 + O1*e1) / (l0*e0 + l1*e1)
// Fully-masked split rows have m = -1e30 -> e = 0 -> contribute nothing.
// ---------------------------------------------------------------------------
__global__ void combine_kernel(float* __restrict__ out)
{
    int idx = blockIdx.x * blockDim.x + threadIdx.x;   // 32*128*1024 = 4194304
    int n = idx & 1023;
    int bv = idx >> 10;            // b*128 + v
    int b = bv >> 7;
    int sb = b * 1024 + n;
    float m0 = g_pm[sb], m1 = g_pm[32 * 1024 + sb];
    float l0 = g_pl[sb], l1 = g_pl[32 * 1024 + sb];
    float M = fmaxf(m0, m1);
    float e0 = __expf(m0 - M), e1 = __expf(m1 - M);
    float denom = l0 * e0 + l1 * e1;
    float O0 = g_po[(size_t)bv * 1024 + n];
    float O1 = g_po[(size_t)(32 * 128 * 1024) + (size_t)bv * 1024 + n];
    out[(size_t)bv * 1024 + n] = (O0 * e0 + O1 * e1) / denom;
}

// ---------------------------------------------------------------------------
// Launch (single stream, graph-capturable)
// ---------------------------------------------------------------------------
extern "C" void kernel_launch(void* const* d_in, const int* in_sizes, int n_in,
                              void* d_out, int out_size)
{
    const float* x   = (const float*)d_in[0];
    const float* k   = (const float*)d_in[1];
    const float* v   = (const float*)d_in[2];
    const float* Wq  = (const float*)d_in[3];
    const float* bq  = (const float*)d_in[4];
    const float* Wfk = (const float*)d_in[5];
    const float* bfk = (const float*)d_in[6];
    const float* Wck = (const float*)d_in[7];
    const float* bck = (const float*)d_in[8];
    const float* Wfv = (const float*)d_in[9];
    const float* bfv = (const float*)d_in[10];
    const float* Wcv = (const float*)d_in[11];
    const float* bcv = (const float*)d_in[12];

    float* out2 = (float*)d_out;
    float* kn   = out2 + (size_t)32 * 128 * 1024;
    float* vn   = kn   + (size_t)32 * 128 * 1024;

    cudaFuncSetAttribute(q_kernel, cudaFuncAttributeMaxDynamicSharedMemorySize, QSMEM_BYTES);
    cudaFuncSetAttribute(mega_kernel, cudaFuncAttributeMaxDynamicSharedMemorySize, MEGA_SMEM_BYTES);

    pos_kernel<<<32, 1024>>>();
    pack_kernel<<<(PACK_TOTAL + 255) / 256, 256>>>(x, k, v, Wq, Wfk, Wck, Wfv, Wcv);
    q_kernel<<<dim3(8, 2, 32), 256, QSMEM_BYTES>>>(bq);
    mega_kernel<<<1536, 256, MEGA_SMEM_BYTES>>>(
        k, v, bfk, bck, bfv, bcv, kn, vn);
    combine_kernel<<<16384, 256>>>(out2);
}

// round 10
// speedup vs baseline: 1.7926x; 1.7926x over previous
#include <cuda_runtime.h>
#include <cuda_fp16.h>
#include <math.h>
#include <stdint.h>

// ---------------------------------------------------------------------------
// Scratch (__device__ globals; no allocation allowed)
// ---------------------------------------------------------------------------
__device__ float  g_pos[32 * 1024];               // [32 ch][1024 n], fp32
__device__ __half g_x0t[(size_t)32 * 1024 * 160]; // [b][n][c]  (x|pos), half
__device__ __half g_kct[(size_t)32 * 1024 * 128]; // [b][m][c]  k transposed
__device__ __half g_vct[(size_t)32 * 1024 * 128]; // [b][m][c]  v transposed
__device__ __half g_vch[(size_t)32 * 128 * 1024]; // [b][c][m]  v (orig orient, half)
__device__ __half g_qt [(size_t)32 * 1024 * 128]; // [b][n][c]  q transposed
__device__ __half g_WqH [128 * 160];              // weights row-major half
__device__ __half g_WfkH[128 * 288];
__device__ __half g_WckH[128 * 288];
__device__ __half g_WfvH[128 * 288];
__device__ __half g_WcvH[128 * 288];

// ---------------------------------------------------------------------------
// Helpers
// ---------------------------------------------------------------------------
__device__ __forceinline__ void mma_f16(
    float& d0, float& d1, float& d2, float& d3,
    uint32_t a0, uint32_t a1, uint32_t a2, uint32_t a3,
    uint32_t b0, uint32_t b1)
{
    asm volatile(
        "mma.sync.aligned.m16n8k16.row.col.f32.f16.f16.f32 "
        "{%0,%1,%2,%3}, {%4,%5,%6,%7}, {%8,%9}, {%0,%1,%2,%3};"
        : "+f"(d0), "+f"(d1), "+f"(d2), "+f"(d3)
        : "r"(a0), "r"(a1), "r"(a2), "r"(a3), "r"(b0), "r"(b1));
}

__device__ __forceinline__ void cpa16(uint32_t dst, const void* src) {
    asm volatile("cp.async.ca.shared.global [%0], [%1], 16;" :: "r"(dst), "l"(src));
}
#define CP_COMMIT() asm volatile("cp.async.commit_group;" ::: "memory")

__device__ __forceinline__ uint32_t h2u(__half2 h) { return *(uint32_t*)&h; }

// ---------------------------------------------------------------------------
// Positional embedding (faithful to numpy .view reinterpret)
// ---------------------------------------------------------------------------
__global__ void pos_kernel() {
    int idx = blockIdx.x * blockDim.x + threadIdx.x;
    if (idx >= 32 * 1024) return;
    int c = idx >> 10, n = idx & 1023;
    int y = n >> 5, x = n & 31;
    int i = (c < 16) ? (c * 32 + y) : ((c - 16) * 32 + x);
    int p = i >> 4, j = i & 15;
    float r = 0.0f;
    if (p != 0) {
        double denom = pow(10000.0, (double)(2 * (j >> 1)) / 16.0);
        double val = (double)p / denom;
        r = (j & 1) ? (float)cos(val) : (float)sin(val);
    }
    g_pos[idx] = r;
}

// ---------------------------------------------------------------------------
// Pack kernel: builds all half tensors.
//   [0,2560)    : x0t transpose tiles  (b:32 × c-tiles:5 × m-tiles:16)
//   [2560,4608) : kct transpose tiles  (b:32 × c-tiles:4 × m-tiles:16)
//   [4608,6656) : vct transpose tiles
//   [6656,8704) : vch straight fp32->half (4M elems)
//   [8704,8786) : weights fp32->half
// ---------------------------------------------------------------------------
#define PACK_BLOCKS 8786

__global__ void pack_kernel(const float* __restrict__ x,
                            const float* __restrict__ k,
                            const float* __restrict__ v,
                            const float* __restrict__ Wq,
                            const float* __restrict__ Wfk, const float* __restrict__ Wck,
                            const float* __restrict__ Wfv, const float* __restrict__ Wcv)
{
    __shared__ __half tile[64][40];     // [m][c] staging for 32c x 64m tiles
    const int j = blockIdx.x, t = threadIdx.x;

    if (j < 2560) {
        // ---- x0t: [b][n][160] from x (c<128) / g_pos (c>=128) ----
        int b = j / 80, rem = j % 80, ct = rem / 16, m_t = rem % 16;
        int c0 = ct * 32, m0 = m_t * 64;
        #pragma unroll
        for (int e = 0; e < 8; e++) {
            int idx = t + 256 * e;
            int ci = idx >> 6, mj = idx & 63;
            int c = c0 + ci;
            float val = (c < 128)
                ? x[((size_t)b * 128 + c) * 1024 + m0 + mj]
                : g_pos[(c - 128) * 1024 + m0 + mj];
            tile[mj][ci] = __float2half_rn(val);
        }
        __syncthreads();
        int mj = t >> 2, c8 = t & 3;
        *(uint4*)(g_x0t + ((size_t)b * 1024 + m0 + mj) * 160 + c0 + c8 * 8) =
            *(uint4*)&tile[mj][c8 * 8];
    } else if (j < 6656) {
        // ---- kct / vct: [b][m][128] transposed ----
        int j2 = j - 2560;
        const float* src = (j2 < 2048) ? k : v;
        __half* dst = (j2 < 2048) ? g_kct : g_vct;
        j2 &= 2047;
        int b = j2 / 64, rem = j2 % 64, ct = rem / 16, m_t = rem % 16;
        int c0 = ct * 32, m0 = m_t * 64;
        #pragma unroll
        for (int e = 0; e < 8; e++) {
            int idx = t + 256 * e;
            int ci = idx >> 6, mj = idx & 63;
            tile[mj][ci] = __float2half_rn(src[((size_t)b * 128 + c0 + ci) * 1024 + m0 + mj]);
        }
        __syncthreads();
        int mj = t >> 2, c8 = t & 3;
        *(uint4*)(dst + ((size_t)b * 1024 + m0 + mj) * 128 + c0 + c8 * 8) =
            *(uint4*)&tile[mj][c8 * 8];
    } else if (j < 8704) {
        // ---- vch: straight convert, same layout as v ----
        int j3 = j - 6656;
        size_t base = (size_t)j3 * 2048 + t * 8;
        const float4* vv = (const float4*)v;
        float4 s0 = vv[base / 4], s1 = vv[base / 4 + 1];
        __half2 h0 = __floats2half2_rn(s0.x, s0.y);
        __half2 h1 = __floats2half2_rn(s0.z, s0.w);
        __half2 h2 = __floats2half2_rn(s1.x, s1.y);
        __half2 h3 = __floats2half2_rn(s1.z, s1.w);
        uint4 o = { h2u(h0), h2u(h1), h2u(h2), h2u(h3) };
        *(uint4*)(g_vch + base) = o;
    } else {
        // ---- weights ----
        int j4 = j - 8704;
        int u0 = j4 * 2048 + t;
        #pragma unroll
        for (int i = 0; i < 8; i++) {
            int u = u0 + i * 256;
            if (u < 20480) {
                g_WqH[u] = __float2half_rn(Wq[u]);
            } else {
                int vv2 = u - 20480;
                int m = vv2 / 36864, o = vv2 % 36864;
                if (m == 0) g_WfkH[o] = __float2half_rn(Wfk[o]);
                else if (m == 1) g_WckH[o] = __float2half_rn(Wck[o]);
                else if (m == 2) g_WfvH[o] = __float2half_rn(Wfv[o]);
                else g_WcvH[o] = __float2half_rn(Wcv[o]);
            }
        }
    }
}

// ---------------------------------------------------------------------------
// Fused GEMM kernel (fp16 MMA):
//   z in [0,64)  : gated highway (z = b*2+which), K=288, 9 tiles of 32
//   z in [64,96) : q = half(relu(Wq@x0+bq)) -> g_qt (transposed epilogue)
// A: W[r][k] half (k-contig). B: rows=spatial n, k-contig (x0t / kct / vct).
// smem strides in u32 (half2) units: ASH=BSH=20 (16 data + 4 pad).
// ---------------------------------------------------------------------------
#define ASH 20
#define BSH 20
#define GBUF_U 5120        // AsF 1280 + AsC 1280 + Bs 2560
#define QBUF_U 3840        // As 1280 + Bs 2560
#define GSMEM_BYTES (2 * GBUF_U * 4)

__global__ __launch_bounds__(256, 2) void fused_gemm_kernel(
    const float* __restrict__ kOrig, const float* __restrict__ vOrig,
    const float* __restrict__ bfk, const float* __restrict__ bck,
    const float* __restrict__ bfv, const float* __restrict__ bcv,
    const float* __restrict__ bq,
    float* __restrict__ outk, float* __restrict__ outv)
{
    extern __shared__ uint32_t smu[];
    const int r0 = blockIdx.y * 64, n0 = blockIdx.x * 128;
    const int t = threadIdx.x, w = t >> 5, lane = t & 31;
    const int lr = lane >> 2, lc = lane & 3;
    const int wm = (w >> 2) * 32;   // 0 / 32
    const int wn = (w & 3) * 32;    // 0,32,64,96
    const uint32_t sbase = (uint32_t)__cvta_generic_to_shared(smu);

    if (blockIdx.z < 64) {
        // ================= gated body =================
        const int z = blockIdx.z, b = z >> 1, which = z & 1;
        const __half* WfH = which ? g_WfvH : g_WfkH;
        const __half* WcH = which ? g_WcvH : g_WckH;
        const float* bfp = which ? bfv : bfk;
        const float* bcp = which ? bcv : bck;
        const __half* extcT = which ? g_vct : g_kct;
        const float* extra = which ? vOrig : kOrig;
        float* out = which ? outv : outk;

        float accF[2][4][4], accC[2][4][4];
        #pragma unroll
        for (int mf = 0; mf < 2; mf++) {
            int rA = r0 + wm + mf * 16 + lr;
            float bf0 = bfp[rA], bf1 = bfp[rA + 8];
            float bc0 = bcp[rA], bc1 = bcp[rA + 8];
            #pragma unroll
            for (int nf = 0; nf < 4; nf++) {
                accF[mf][nf][0] = bf0; accF[mf][nf][1] = bf0;
                accF[mf][nf][2] = bf1; accF[mf][nf][3] = bf1;
                accC[mf][nf][0] = bc0; accC[mf][nf][1] = bc0;
                accC[mf][nf][2] = bc1; accC[mf][nf][3] = bc1;
            }
        }

        auto issue = [&](int it, int buf) {
            const int k0 = it * 32;
            const uint32_t base = sbase + buf * (GBUF_U * 4);
            {   // A: 64 rows x 32 halves x 2 mats, 1 chunk per thread per mat
                int r = t >> 2, c4 = t & 3;
                cpa16(base + (r * ASH + c4 * 4) * 4,
                      WfH + (size_t)(r0 + r) * 288 + k0 + c4 * 8);
                cpa16(base + (1280 + r * ASH + c4 * 4) * 4,
                      WcH + (size_t)(r0 + r) * 288 + k0 + c4 * 8);
            }
            #pragma unroll
            for (int h = 0; h < 2; h++) {   // B: 128 rows x 4 chunks
                int idx = t + 256 * h;
                int r = idx >> 2, c4 = idx & 3;
                const __half* src = (k0 < 160)
                    ? (g_x0t + ((size_t)b * 1024 + n0 + r) * 160 + k0 + c4 * 8)
                    : (extcT + ((size_t)b * 1024 + n0 + r) * 128 + (k0 - 160) + c4 * 8);
                cpa16(base + (2560 + r * BSH + c4 * 4) * 4, src);
            }
            CP_COMMIT();
        };

        issue(0, 0);
        #pragma unroll 1
        for (int it = 0; it < 9; it++) {
            if (it < 8) {
                issue(it + 1, (it + 1) & 1);
                asm volatile("cp.async.wait_group 1;" ::: "memory");
            } else {
                asm volatile("cp.async.wait_group 0;" ::: "memory");
            }
            __syncthreads();

            const uint32_t* AsF = smu + (it & 1) * GBUF_U;
            const uint32_t* AsC = AsF + 1280;
            const uint32_t* Bs  = AsF + 2560;

            #pragma unroll
            for (int kf = 0; kf < 2; kf++) {
                uint32_t aF[2][4], aC[2][4], bb[4][2];
                #pragma unroll
                for (int mf = 0; mf < 2; mf++) {
                    int base = (wm + mf * 16 + lr) * ASH + kf * 8 + lc;
                    aF[mf][0] = AsF[base];
                    aF[mf][1] = AsF[base + 8 * ASH];
                    aF[mf][2] = AsF[base + 4];
                    aF[mf][3] = AsF[base + 8 * ASH + 4];
                    aC[mf][0] = AsC[base];
                    aC[mf][1] = AsC[base + 8 * ASH];
                    aC[mf][2] = AsC[base + 4];
                    aC[mf][3] = AsC[base + 8 * ASH + 4];
                }
                #pragma unroll
                for (int nf = 0; nf < 4; nf++) {
                    int base = (wn + nf * 8 + lr) * BSH + kf * 8 + lc;
                    bb[nf][0] = Bs[base];
                    bb[nf][1] = Bs[base + 4];
                }
                #pragma unroll
                for (int mf = 0; mf < 2; mf++)
                    #pragma unroll
                    for (int nf = 0; nf < 4; nf++) {
                        mma_f16(accF[mf][nf][0], accF[mf][nf][1], accF[mf][nf][2], accF[mf][nf][3],
                                aF[mf][0], aF[mf][1], aF[mf][2], aF[mf][3], bb[nf][0], bb[nf][1]);
                        mma_f16(accC[mf][nf][0], accC[mf][nf][1], accC[mf][nf][2], accC[mf][nf][3],
                                aC[mf][0], aC[mf][1], aC[mf][2], aC[mf][3], bb[nf][0], bb[nf][1]);
                    }
            }
            __syncthreads();
        }

        #pragma unroll
        for (int mf = 0; mf < 2; mf++) {
            int rA = r0 + wm + mf * 16 + lr;
            #pragma unroll
            for (int nf = 0; nf < 4; nf++) {
                int n = n0 + wn + nf * 8 + 2 * lc;
                #pragma unroll
                for (int h = 0; h < 2; h++) {
                    int row = rA + h * 8;
                    #pragma unroll
                    for (int jj = 0; jj < 2; jj++) {
                        float F  = accF[mf][nf][2 * h + jj];
                        float Cc = accC[mf][nf][2 * h + jj];
                        float f  = 1.0f / (1.0f + __expf(-F));
                        float cc = fmaxf(Cc, 0.0f);
                        size_t off = ((size_t)(b * 128 + row)) * 1024 + n + jj;
                        out[off] = f * extra[off] + cc;
                    }
                }
            }
        }
    } else {
        // ================= q body =================
        const int b = blockIdx.z - 64;

        float acc[2][4][4];
        #pragma unroll
        for (int mf = 0; mf < 2; mf++) {
            int rA = r0 + wm + mf * 16 + lr;
            float b0 = bq[rA], b1 = bq[rA + 8];
            #pragma unroll
            for (int nf = 0; nf < 4; nf++) {
                acc[mf][nf][0] = b0; acc[mf][nf][1] = b0;
                acc[mf][nf][2] = b1; acc[mf][nf][3] = b1;
            }
        }

        auto issue = [&](int it, int buf) {
            const int k0 = it * 32;
            const uint32_t base = sbase + buf * (QBUF_U * 4);
            {
                int r = t >> 2, c4 = t & 3;
                cpa16(base + (r * ASH + c4 * 4) * 4,
                      g_WqH + (size_t)(r0 + r) * 160 + k0 + c4 * 8);
            }
            #pragma unroll
            for (int h = 0; h < 2; h++) {
                int idx = t + 256 * h;
                int r = idx >> 2, c4 = idx & 3;
                cpa16(base + (1280 + r * BSH + c4 * 4) * 4,
                      g_x0t + ((size_t)b * 1024 + n0 + r) * 160 + k0 + c4 * 8);
            }
            CP_COMMIT();
        };

        issue(0, 0);
        #pragma unroll 1
        for (int it = 0; it < 5; it++) {
            if (it < 4) {
                issue(it + 1, (it + 1) & 1);
                asm volatile("cp.async.wait_group 1;" ::: "memory");
            } else {
                asm volatile("cp.async.wait_group 0;" ::: "memory");
            }
            __syncthreads();

            const uint32_t* As = smu + (it & 1) * QBUF_U;
            const uint32_t* Bs = As + 1280;

            #pragma unroll
            for (int kf = 0; kf < 2; kf++) {
                uint32_t aa[2][4], bb[4][2];
                #pragma unroll
                for (int mf = 0; mf < 2; mf++) {
                    int base = (wm + mf * 16 + lr) * ASH + kf * 8 + lc;
                    aa[mf][0] = As[base];
                    aa[mf][1] = As[base + 8 * ASH];
                    aa[mf][2] = As[base + 4];
                    aa[mf][3] = As[base + 8 * ASH + 4];
                }
                #pragma unroll
                for (int nf = 0; nf < 4; nf++) {
                    int base = (wn + nf * 8 + lr) * BSH + kf * 8 + lc;
                    bb[nf][0] = Bs[base];
                    bb[nf][1] = Bs[base + 4];
                }
                #pragma unroll
                for (int mf = 0; mf < 2; mf++)
                    #pragma unroll
                    for (int nf = 0; nf < 4; nf++)
                        mma_f16(acc[mf][nf][0], acc[mf][nf][1], acc[mf][nf][2], acc[mf][nf][3],
                                aa[mf][0], aa[mf][1], aa[mf][2], aa[mf][3], bb[nf][0], bb[nf][1]);
            }
            __syncthreads();
        }

        // Transposed epilogue: stage tile [n_local 128][c_local 64] halves, then
        // write g_qt[b][n][c] coalesced. Staging stride 72 halves (36 u32).
        __half* stg = (__half*)smu;
        #pragma unroll
        for (int mf = 0; mf < 2; mf++) {
            int cl = wm + mf * 16 + lr;
            #pragma unroll
            for (int nf = 0; nf < 4; nf++) {
                int nl = wn + nf * 8 + 2 * lc;
                #pragma unroll
                for (int h = 0; h < 2; h++) {
                    int c = cl + h * 8;
                    stg[(nl)     * 72 + c] = __float2half_rn(fmaxf(acc[mf][nf][2 * h],     0.0f));
                    stg[(nl + 1) * 72 + c] = __float2half_rn(fmaxf(acc[mf][nf][2 * h + 1], 0.0f));
                }
            }
        }
        __syncthreads();
        #pragma unroll
        for (int h = 0; h < 4; h++) {
            int idx = t + 256 * h;          // 0..1023 = 128 rows x 8 chunks
            int n = idx >> 3, c8 = idx & 7;
            uint4 d = *(uint4*)&stg[n * 72 + c8 * 8];
            *(uint4*)(g_qt + ((size_t)b * 1024 + n0 + n) * 128 + r0 + c8 * 8) = d;
        }
    }
}

// ---------------------------------------------------------------------------
// Causal attention, fp16 FA2-style (R8 structure):
//   - Q fragments register-resident from g_qt (32 u32)
//   - K [m][c] / V [c][m] half tiles, double-buffered, ONE barrier per iter
//   - warp-owned 16 q-rows x 64 keys (S) / x 128 v-channels (PV)
//   - softmax in registers; P half2 in warp-private smem strip
// smem (u32): Ks 64x68 x2 + Vs 128x36 x2 + Ps 128x36 = 22528 u32 = 90112 B.
// ---------------------------------------------------------------------------
#define SKH 68
#define SVH 36
#define SPH 36
#define KS_U (64 * SKH)                 // 4352
#define VS_U (128 * SVH)                // 4608
#define A_KS0 0
#define A_KS1 KS_U
#define A_VS0 (2 * KS_U)
#define A_VS1 (2 * KS_U + VS_U)
#define A_PS  (2 * KS_U + 2 * VS_U)     // 17920
#define ATTN_SMEM_U (A_PS + 128 * SPH)  // 22528
#define ATTN_SMEM_BYTES (ATTN_SMEM_U * 4)

__global__ __launch_bounds__(256, 1) void attn_kernel(float* __restrict__ out)
{
    extern __shared__ uint32_t smu[];
    uint32_t* Ps = smu + A_PS;

    const int id = blockIdx.x;
    const int qt = 7 - (id >> 5);         // heavy q-tiles first (LPT)
    const int b = id & 31;
    const int n0 = qt * 128;
    const int mtMax = 2 * qt + 1;
    const int t = threadIdx.x, w = t >> 5, lane = t & 31;
    const int lr = lane >> 2, lc = lane & 3;
    const int wq = w * 16;
    const float scale = 0.08838834764831845f;
    const uint32_t sbase = (uint32_t)__cvta_generic_to_shared(smu);

    auto issue_stage = [&](int mt) {
        const int p = mt & 1;
        const int m0 = mt * 64;
        const uint32_t kb = sbase + (p ? A_KS1 : A_KS0) * 4;
        const uint32_t vb = sbase + (p ? A_VS1 : A_VS0) * 4;
        #pragma unroll
        for (int h = 0; h < 4; h++) {     // K: 64 rows x 16 chunks (256B/row)
            int idx = t + 256 * h;
            int m = idx >> 4, c16 = idx & 15;
            cpa16(kb + (m * SKH + c16 * 4) * 4,
                  g_kct + ((size_t)b * 1024 + m0 + m) * 128 + c16 * 8);
        }
        #pragma unroll
        for (int h = 0; h < 4; h++) {     // V: 128 rows x 8 chunks (128B/row)
            int idx = t + 256 * h;
            int c = idx >> 3, m16 = idx & 7;
            cpa16(vb + (c * SVH + m16 * 4) * 4,
                  g_vch + ((size_t)b * 128 + c) * 1024 + m0 + m16 * 8);
        }
        CP_COMMIT();
    };

    issue_stage(0);

    // Q fragments: qa[kf] covers channels kf*16..+15, rows wq+lr / +8.
    uint32_t qa[8][4];
    {
        const __half* qp = g_qt + ((size_t)b * 1024 + n0 + wq + lr) * 128;
        #pragma unroll
        for (int kf = 0; kf < 8; kf++) {
            qa[kf][0] = *(const uint32_t*)(qp + kf * 16 + 2 * lc);
            qa[kf][1] = *(const uint32_t*)(qp + 8 * 128 + kf * 16 + 2 * lc);
            qa[kf][2] = *(const uint32_t*)(qp + kf * 16 + 2 * lc + 8);
            qa[kf][3] = *(const uint32_t*)(qp + 8 * 128 + kf * 16 + 2 * lc + 8);
        }
    }

    float mLo = -1e30f, mHi = -1e30f, lLo = 0.0f, lHi = 0.0f;
    float O[16][4];
    #pragma unroll
    for (int nb = 0; nb < 16; nb++)
        #pragma unroll
        for (int jj = 0; jj < 4; jj++) O[nb][jj] = 0.0f;

    const int rowLo = n0 + wq + lr;
    const int rowHi = rowLo + 8;

    #pragma unroll 1
    for (int mt = 0; mt <= mtMax; mt++) {
        const int m0 = mt * 64;
        const uint32_t* Ks = smu + ((mt & 1) ? A_KS1 : A_KS0);
        const uint32_t* Vs = smu + ((mt & 1) ? A_VS1 : A_VS0);

        asm volatile("cp.async.wait_group 0;" ::: "memory");
        __syncthreads();
        if (mt < mtMax) issue_stage(mt + 1);

        // ---- S = Q K^T : warp tile 16 x 64, contract c=128 (8 k16 steps) ----
        float S[8][4];
        #pragma unroll
        for (int nb = 0; nb < 8; nb++)
            #pragma unroll
            for (int jj = 0; jj < 4; jj++) S[nb][jj] = 0.0f;

        #pragma unroll
        for (int kf = 0; kf < 8; kf++) {
            #pragma unroll
            for (int nb = 0; nb < 8; nb++) {
                int bbase = (nb * 8 + lr) * SKH + kf * 8 + lc;
                mma_f16(S[nb][0], S[nb][1], S[nb][2], S[nb][3],
                        qa[kf][0], qa[kf][1], qa[kf][2], qa[kf][3],
                        Ks[bbase], Ks[bbase + 4]);
            }
        }

        // ---- In-register online softmax (warp-local) ----
        {
            const bool needMask = (m0 + 63 > n0 + wq);
            float tmLo = -1e30f, tmHi = -1e30f;
            #pragma unroll
            for (int nb = 0; nb < 8; nb++) {
                int c0 = m0 + nb * 8 + 2 * lc, c1 = c0 + 1;
                float s0 = S[nb][0] * scale, s1 = S[nb][1] * scale;
                float s2 = S[nb][2] * scale, s3 = S[nb][3] * scale;
                if (needMask) {
                    if (c0 > rowLo) s0 = -1e30f;
                    if (c1 > rowLo) s1 = -1e30f;
                    if (c0 > rowHi) s2 = -1e30f;
                    if (c1 > rowHi) s3 = -1e30f;
                }
                S[nb][0] = s0; S[nb][1] = s1; S[nb][2] = s2; S[nb][3] = s3;
                tmLo = fmaxf(tmLo, fmaxf(s0, s1));
                tmHi = fmaxf(tmHi, fmaxf(s2, s3));
            }
            tmLo = fmaxf(tmLo, __shfl_xor_sync(0xffffffffu, tmLo, 1));
            tmLo = fmaxf(tmLo, __shfl_xor_sync(0xffffffffu, tmLo, 2));
            tmHi = fmaxf(tmHi, __shfl_xor_sync(0xffffffffu, tmHi, 1));
            tmHi = fmaxf(tmHi, __shfl_xor_sync(0xffffffffu, tmHi, 2));
            float nmLo = fmaxf(mLo, tmLo), nmHi = fmaxf(mHi, tmHi);
            float aLo = __expf(mLo - nmLo), aHi = __expf(mHi - nmHi);
            mLo = nmLo; mHi = nmHi;
            float sLoSum = 0.0f, sHiSum = 0.0f;
            #pragma unroll
            for (int nb = 0; nb < 8; nb++) {
                float p0 = __expf(S[nb][0] - nmLo);
                float p1 = __expf(S[nb][1] - nmLo);
                float p2 = __expf(S[nb][2] - nmHi);
                float p3 = __expf(S[nb][3] - nmHi);
                sLoSum += p0 + p1;
                sHiSum += p2 + p3;
                Ps[(wq + lr) * SPH + nb * 4 + lc]     = h2u(__floats2half2_rn(p0, p1));
                Ps[(wq + lr + 8) * SPH + nb * 4 + lc] = h2u(__floats2half2_rn(p2, p3));
            }
            sLoSum += __shfl_xor_sync(0xffffffffu, sLoSum, 1);
            sLoSum += __shfl_xor_sync(0xffffffffu, sLoSum, 2);
            sHiSum += __shfl_xor_sync(0xffffffffu, sHiSum, 1);
            sHiSum += __shfl_xor_sync(0xffffffffu, sHiSum, 2);
            lLo = lLo * aLo + sLoSum;
            lHi = lHi * aHi + sHiSum;
            #pragma unroll
            for (int nb = 0; nb < 16; nb++) {
                O[nb][0] *= aLo; O[nb][1] *= aLo;
                O[nb][2] *= aHi; O[nb][3] *= aHi;
            }
        }
        __syncwarp();   // Ps strip is warp-private

        // ---- O += P V^T : 16 rows x 128 v-channels, contract keys (4 k16) ----
        #pragma unroll
        for (int kf = 0; kf < 4; kf++) {
            int ab = (wq + lr) * SPH + kf * 8 + lc;
            uint32_t a0 = Ps[ab];
            uint32_t a1 = Ps[ab + 8 * SPH];
            uint32_t a2 = Ps[ab + 4];
            uint32_t a3 = Ps[ab + 8 * SPH + 4];
            #pragma unroll
            for (int nb = 0; nb < 16; nb++) {
                int bb = (nb * 8 + lr) * SVH + kf * 8 + lc;
                mma_f16(O[nb][0], O[nb][1], O[nb][2], O[nb][3],
                        a0, a1, a2, a3, Vs[bb], Vs[bb + 4]);
            }
        }
        // next iteration's top barrier protects buffer reuse
    }

    float iLo = 1.0f / lLo, iHi = 1.0f / lHi;
    #pragma unroll
    for (int nb = 0; nb < 16; nb++) {
        int vc = nb * 8 + 2 * lc;
        out[((size_t)(b * 128 + vc))     * 1024 + rowLo] = O[nb][0] * iLo;
        out[((size_t)(b * 128 + vc + 1)) * 1024 + rowLo] = O[nb][1] * iLo;
        out[((size_t)(b * 128 + vc))     * 1024 + rowHi] = O[nb][2] * iHi;
        out[((size_t)(b * 128 + vc + 1)) * 1024 + rowHi] = O[nb][3] * iHi;
    }
}

// ---------------------------------------------------------------------------
// Launch (single stream, graph-capturable)
// ---------------------------------------------------------------------------
extern "C" void kernel_launch(void* const* d_in, const int* in_sizes, int n_in,
                              void* d_out, int out_size)
{
    const float* x   = (const float*)d_in[0];
    const float* k   = (const float*)d_in[1];
    const float* v   = (const float*)d_in[2];
    const float* Wq  = (const float*)d_in[3];
    const float* bq  = (const float*)d_in[4];
    const float* Wfk = (const float*)d_in[5];
    const float* bfk = (const float*)d_in[6];
    const float* Wck = (const float*)d_in[7];
    const float* bck = (const float*)d_in[8];
    const float* Wfv = (const float*)d_in[9];
    const float* bfv = (const float*)d_in[10];
    const float* Wcv = (const float*)d_in[11];
    const float* bcv = (const float*)d_in[12];

    float* out2 = (float*)d_out;
    float* kn   = out2 + (size_t)32 * 128 * 1024;
    float* vn   = kn   + (size_t)32 * 128 * 1024;

    cudaFuncSetAttribute(fused_gemm_kernel, cudaFuncAttributeMaxDynamicSharedMemorySize, GSMEM_BYTES);
    cudaFuncSetAttribute(attn_kernel, cudaFuncAttributeMaxDynamicSharedMemorySize, ATTN_SMEM_BYTES);

    pos_kernel<<<32, 1024>>>();
    pack_kernel<<<PACK_BLOCKS, 256>>>(x, k, v, Wq, Wfk, Wck, Wfv, Wcv);
    fused_gemm_kernel<<<dim3(8, 2, 96), 256, GSMEM_BYTES>>>(
        k, v, bfk, bck, bfv, bcv, bq, kn, vn);
    attn_kernel<<<256, 256, ATTN_SMEM_BYTES>>>(out2);
}

// round 11
// speedup vs baseline: 1.8175x; 1.0139x over previous
#include <cuda_runtime.h>
#include <cuda_fp16.h>
#include <math.h>
#include <stdint.h>

// ---------------------------------------------------------------------------
// Scratch (__device__ globals; no allocation allowed)
// ---------------------------------------------------------------------------
__device__ float  g_pos[32 * 1024];               // [32 ch][1024 n], fp32
__device__ __half g_x0t[(size_t)32 * 1024 * 160]; // [b][n][c]  (x|pos), half
__device__ __half g_kct[(size_t)32 * 1024 * 128]; // [b][m][c]  k transposed
__device__ __half g_vct[(size_t)32 * 1024 * 128]; // [b][m][c]  v transposed
__device__ __half g_vch[(size_t)32 * 128 * 1024]; // [b][c][m]  v (orig orient, half)
__device__ __half g_qt [(size_t)32 * 1024 * 128]; // [b][n][c]  q transposed
__device__ __half g_WqH [128 * 160];              // weights row-major half
__device__ __half g_WfkH[128 * 288];
__device__ __half g_WckH[128 * 288];
__device__ __half g_WfvH[128 * 288];
__device__ __half g_WcvH[128 * 288];

// ---------------------------------------------------------------------------
// Helpers
// ---------------------------------------------------------------------------
__device__ __forceinline__ void mma_f16(
    float& d0, float& d1, float& d2, float& d3,
    uint32_t a0, uint32_t a1, uint32_t a2, uint32_t a3,
    uint32_t b0, uint32_t b1)
{
    asm volatile(
        "mma.sync.aligned.m16n8k16.row.col.f32.f16.f16.f32 "
        "{%0,%1,%2,%3}, {%4,%5,%6,%7}, {%8,%9}, {%0,%1,%2,%3};"
        : "+f"(d0), "+f"(d1), "+f"(d2), "+f"(d3)
        : "r"(a0), "r"(a1), "r"(a2), "r"(a3), "r"(b0), "r"(b1));
}

__device__ __forceinline__ void cpa16(uint32_t dst, const void* src) {
    asm volatile("cp.async.ca.shared.global [%0], [%1], 16;" :: "r"(dst), "l"(src));
}
#define CP_COMMIT() asm volatile("cp.async.commit_group;" ::: "memory")

__device__ __forceinline__ uint32_t h2u(__half2 h) { return *(uint32_t*)&h; }

// ---------------------------------------------------------------------------
// Positional embedding (faithful to numpy .view reinterpret)
// ---------------------------------------------------------------------------
__global__ void pos_kernel() {
    int idx = blockIdx.x * blockDim.x + threadIdx.x;
    if (idx >= 32 * 1024) return;
    int c = idx >> 10, n = idx & 1023;
    int y = n >> 5, x = n & 31;
    int i = (c < 16) ? (c * 32 + y) : ((c - 16) * 32 + x);
    int p = i >> 4, j = i & 15;
    float r = 0.0f;
    if (p != 0) {
        double denom = pow(10000.0, (double)(2 * (j >> 1)) / 16.0);
        double val = (double)p / denom;
        r = (j & 1) ? (float)cos(val) : (float)sin(val);
    }
    g_pos[idx] = r;
}

// ---------------------------------------------------------------------------
// Pack kernel: builds all half tensors.
//   [0,2560)    : x0t transpose tiles  (b:32 × c-tiles:5 × m-tiles:16)
//   [2560,4608) : kct transpose tiles  (b:32 × c-tiles:4 × m-tiles:16)
//   [4608,6656) : vct transpose tiles  (ALSO writes vch from the same read)
//   [6656,6738) : weights fp32->half
// ---------------------------------------------------------------------------
#define PACK_BLOCKS 6738

__global__ void pack_kernel(const float* __restrict__ x,
                            const float* __restrict__ k,
                            const float* __restrict__ v,
                            const float* __restrict__ Wq,
                            const float* __restrict__ Wfk, const float* __restrict__ Wck,
                            const float* __restrict__ Wfv, const float* __restrict__ Wcv)
{
    __shared__ __half tile[64][40];     // [m][c] staging for 32c x 64m tiles
    const int j = blockIdx.x, t = threadIdx.x;

    if (j < 2560) {
        // ---- x0t: [b][n][160] from x (c<128) / g_pos (c>=128) ----
        int b = j / 80, rem = j % 80, ct = rem / 16, m_t = rem % 16;
        int c0 = ct * 32, m0 = m_t * 64;
        #pragma unroll
        for (int e = 0; e < 8; e++) {
            int idx = t + 256 * e;
            int ci = idx >> 6, mj = idx & 63;
            int c = c0 + ci;
            float val = (c < 128)
                ? x[((size_t)b * 128 + c) * 1024 + m0 + mj]
                : g_pos[(c - 128) * 1024 + m0 + mj];
            tile[mj][ci] = __float2half_rn(val);
        }
        __syncthreads();
        int mj = t >> 2, c8 = t & 3;
        *(uint4*)(g_x0t + ((size_t)b * 1024 + m0 + mj) * 160 + c0 + c8 * 8) =
            *(uint4*)&tile[mj][c8 * 8];
    } else if (j < 6656) {
        // ---- kct / vct: [b][m][128] transposed; vct branch also emits vch ----
        int j2 = j - 2560;
        const bool isV = (j2 >= 2048);
        const float* src = isV ? v : k;
        __half* dst = isV ? g_vct : g_kct;
        j2 &= 2047;
        int b = j2 / 64, rem = j2 % 64, ct = rem / 16, m_t = rem % 16;
        int c0 = ct * 32, m0 = m_t * 64;
        #pragma unroll
        for (int e = 0; e < 8; e++) {
            int idx = t + 256 * e;
            int ci = idx >> 6, mj = idx & 63;
            __half h = __float2half_rn(src[((size_t)b * 128 + c0 + ci) * 1024 + m0 + mj]);
            tile[mj][ci] = h;
            if (isV)
                g_vch[((size_t)b * 128 + c0 + ci) * 1024 + m0 + mj] = h;
        }
        __syncthreads();
        int mj = t >> 2, c8 = t & 3;
        *(uint4*)(dst + ((size_t)b * 1024 + m0 + mj) * 128 + c0 + c8 * 8) =
            *(uint4*)&tile[mj][c8 * 8];
    } else {
        // ---- weights ----
        int j4 = j - 6656;
        int u0 = j4 * 2048 + t;
        #pragma unroll
        for (int i = 0; i < 8; i++) {
            int u = u0 + i * 256;
            if (u < 20480) {
                g_WqH[u] = __float2half_rn(Wq[u]);
            } else {
                int vv2 = u - 20480;
                int m = vv2 / 36864, o = vv2 % 36864;
                if (m == 0) g_WfkH[o] = __float2half_rn(Wfk[o]);
                else if (m == 1) g_WckH[o] = __float2half_rn(Wck[o]);
                else if (m == 2) g_WfvH[o] = __float2half_rn(Wfv[o]);
                else g_WcvH[o] = __float2half_rn(Wcv[o]);
            }
        }
    }
}

// ---------------------------------------------------------------------------
// Fused GEMM kernel (fp16 MMA), 3-stage cp.async ring, ONE barrier per iter:
//   z in [0,64)  : gated highway (z = b*2+which), K=288, 9 tiles of 32
//   z in [64,96) : q = half(relu(Wq@x0+bq)) -> g_qt (transposed epilogue)
// smem strides in u32 (half2) units: ASH=BSH=20 (16 data + 4 pad).
// Ring: 3 x GBUF_U = 15360 u32 = 61440 B; 2 CTAs/SM = 122880 B.
// ---------------------------------------------------------------------------
#define ASH 20
#define BSH 20
#define GBUF_U 5120        // AsF 1280 + AsC 1280 + Bs 2560
#define QBUF_U 3840        // As 1280 + Bs 2560
#define GSMEM_BYTES (3 * GBUF_U * 4)

__global__ __launch_bounds__(256, 2) void fused_gemm_kernel(
    const float* __restrict__ kOrig, const float* __restrict__ vOrig,
    const float* __restrict__ bfk, const float* __restrict__ bck,
    const float* __restrict__ bfv, const float* __restrict__ bcv,
    const float* __restrict__ bq,
    float* __restrict__ outk, float* __restrict__ outv)
{
    extern __shared__ uint32_t smu[];
    const int r0 = blockIdx.y * 64, n0 = blockIdx.x * 128;
    const int t = threadIdx.x, w = t >> 5, lane = t & 31;
    const int lr = lane >> 2, lc = lane & 3;
    const int wm = (w >> 2) * 32;   // 0 / 32
    const int wn = (w & 3) * 32;    // 0,32,64,96
    const uint32_t sbase = (uint32_t)__cvta_generic_to_shared(smu);

    if (blockIdx.z < 64) {
        // ================= gated body =================
        const int z = blockIdx.z, b = z >> 1, which = z & 1;
        const __half* WfH = which ? g_WfvH : g_WfkH;
        const __half* WcH = which ? g_WcvH : g_WckH;
        const float* bfp = which ? bfv : bfk;
        const float* bcp = which ? bcv : bck;
        const __half* extcT = which ? g_vct : g_kct;
        const float* extra = which ? vOrig : kOrig;
        float* out = which ? outv : outk;

        float accF[2][4][4], accC[2][4][4];
        #pragma unroll
        for (int mf = 0; mf < 2; mf++) {
            int rA = r0 + wm + mf * 16 + lr;
            float bf0 = bfp[rA], bf1 = bfp[rA + 8];
            float bc0 = bcp[rA], bc1 = bcp[rA + 8];
            #pragma unroll
            for (int nf = 0; nf < 4; nf++) {
                accF[mf][nf][0] = bf0; accF[mf][nf][1] = bf0;
                accF[mf][nf][2] = bf1; accF[mf][nf][3] = bf1;
                accC[mf][nf][0] = bc0; accC[mf][nf][1] = bc0;
                accC[mf][nf][2] = bc1; accC[mf][nf][3] = bc1;
            }
        }

        auto issue = [&](int it, int buf) {
            const int k0 = it * 32;
            const uint32_t base = sbase + buf * (GBUF_U * 4);
            {
                int r = t >> 2, c4 = t & 3;
                cpa16(base + (r * ASH + c4 * 4) * 4,
                      WfH + (size_t)(r0 + r) * 288 + k0 + c4 * 8);
                cpa16(base + (1280 + r * ASH + c4 * 4) * 4,
                      WcH + (size_t)(r0 + r) * 288 + k0 + c4 * 8);
            }
            #pragma unroll
            for (int h = 0; h < 2; h++) {
                int idx = t + 256 * h;
                int r = idx >> 2, c4 = idx & 3;
                const __half* src = (k0 < 160)
                    ? (g_x0t + ((size_t)b * 1024 + n0 + r) * 160 + k0 + c4 * 8)
                    : (extcT + ((size_t)b * 1024 + n0 + r) * 128 + (k0 - 160) + c4 * 8);
                cpa16(base + (2560 + r * BSH + c4 * 4) * 4, src);
            }
            CP_COMMIT();
        };

        issue(0, 0);
        issue(1, 1);
        #pragma unroll 1
        for (int it = 0; it < 9; it++) {
            if (it < 8) {
                asm volatile("cp.async.wait_group 1;" ::: "memory");
            } else {
                asm volatile("cp.async.wait_group 0;" ::: "memory");
            }
            __syncthreads();
            if (it + 2 <= 8) issue(it + 2, (it + 2) % 3);

            const uint32_t* AsF = smu + (it % 3) * GBUF_U;
            const uint32_t* AsC = AsF + 1280;
            const uint32_t* Bs  = AsF + 2560;

            #pragma unroll
            for (int kf = 0; kf < 2; kf++) {
                uint32_t aF[2][4], aC[2][4], bb[4][2];
                #pragma unroll
                for (int mf = 0; mf < 2; mf++) {
                    int base = (wm + mf * 16 + lr) * ASH + kf * 8 + lc;
                    aF[mf][0] = AsF[base];
                    aF[mf][1] = AsF[base + 8 * ASH];
                    aF[mf][2] = AsF[base + 4];
                    aF[mf][3] = AsF[base + 8 * ASH + 4];
                    aC[mf][0] = AsC[base];
                    aC[mf][1] = AsC[base + 8 * ASH];
                    aC[mf][2] = AsC[base + 4];
                    aC[mf][3] = AsC[base + 8 * ASH + 4];
                }
                #pragma unroll
                for (int nf = 0; nf < 4; nf++) {
                    int base = (wn + nf * 8 + lr) * BSH + kf * 8 + lc;
                    bb[nf][0] = Bs[base];
                    bb[nf][1] = Bs[base + 4];
                }
                #pragma unroll
                for (int mf = 0; mf < 2; mf++)
                    #pragma unroll
                    for (int nf = 0; nf < 4; nf++) {
                        mma_f16(accF[mf][nf][0], accF[mf][nf][1], accF[mf][nf][2], accF[mf][nf][3],
                                aF[mf][0], aF[mf][1], aF[mf][2], aF[mf][3], bb[nf][0], bb[nf][1]);
                        mma_f16(accC[mf][nf][0], accC[mf][nf][1], accC[mf][nf][2], accC[mf][nf][3],
                                aC[mf][0], aC[mf][1], aC[mf][2], aC[mf][3], bb[nf][0], bb[nf][1]);
                    }
            }
            // no trailing barrier: next iteration's top barrier protects reuse
        }

        #pragma unroll
        for (int mf = 0; mf < 2; mf++) {
            int rA = r0 + wm + mf * 16 + lr;
            #pragma unroll
            for (int nf = 0; nf < 4; nf++) {
                int n = n0 + wn + nf * 8 + 2 * lc;
                #pragma unroll
                for (int h = 0; h < 2; h++) {
                    int row = rA + h * 8;
                    #pragma unroll
                    for (int jj = 0; jj < 2; jj++) {
                        float F  = accF[mf][nf][2 * h + jj];
                        float Cc = accC[mf][nf][2 * h + jj];
                        float f  = 1.0f / (1.0f + __expf(-F));
                        float cc = fmaxf(Cc, 0.0f);
                        size_t off = ((size_t)(b * 128 + row)) * 1024 + n + jj;
                        out[off] = f * extra[off] + cc;
                    }
                }
            }
        }
    } else {
        // ================= q body =================
        const int b = blockIdx.z - 64;

        float acc[2][4][4];
        #pragma unroll
        for (int mf = 0; mf < 2; mf++) {
            int rA = r0 + wm + mf * 16 + lr;
            float b0 = bq[rA], b1 = bq[rA + 8];
            #pragma unroll
            for (int nf = 0; nf < 4; nf++) {
                acc[mf][nf][0] = b0; acc[mf][nf][1] = b0;
                acc[mf][nf][2] = b1; acc[mf][nf][3] = b1;
            }
        }

        auto issue = [&](int it, int buf) {
            const int k0 = it * 32;
            const uint32_t base = sbase + buf * (QBUF_U * 4);
            {
                int r = t >> 2, c4 = t & 3;
                cpa16(base + (r * ASH + c4 * 4) * 4,
                      g_WqH + (size_t)(r0 + r) * 160 + k0 + c4 * 8);
            }
            #pragma unroll
            for (int h = 0; h < 2; h++) {
                int idx = t + 256 * h;
                int r = idx >> 2, c4 = idx & 3;
                cpa16(base + (1280 + r * BSH + c4 * 4) * 4,
                      g_x0t + ((size_t)b * 1024 + n0 + r) * 160 + k0 + c4 * 8);
            }
            CP_COMMIT();
        };

        issue(0, 0);
        issue(1, 1);
        #pragma unroll 1
        for (int it = 0; it < 5; it++) {
            if (it < 4) {
                asm volatile("cp.async.wait_group 1;" ::: "memory");
            } else {
                asm volatile("cp.async.wait_group 0;" ::: "memory");
            }
            __syncthreads();
            if (it + 2 <= 4) issue(it + 2, (it + 2) % 3);

            const uint32_t* As = smu + (it % 3) * QBUF_U;
            const uint32_t* Bs = As + 1280;

            #pragma unroll
            for (int kf = 0; kf < 2; kf++) {
                uint32_t aa[2][4], bb[4][2];
                #pragma unroll
                for (int mf = 0; mf < 2; mf++) {
                    int base = (wm + mf * 16 + lr) * ASH + kf * 8 + lc;
                    aa[mf][0] = As[base];
                    aa[mf][1] = As[base + 8 * ASH];
                    aa[mf][2] = As[base + 4];
                    aa[mf][3] = As[base + 8 * ASH + 4];
                }
                #pragma unroll
                for (int nf = 0; nf < 4; nf++) {
                    int base = (wn + nf * 8 + lr) * BSH + kf * 8 + lc;
                    bb[nf][0] = Bs[base];
                    bb[nf][1] = Bs[base + 4];
                }
                #pragma unroll
                for (int mf = 0; mf < 2; mf++)
                    #pragma unroll
                    for (int nf = 0; nf < 4; nf++)
                        mma_f16(acc[mf][nf][0], acc[mf][nf][1], acc[mf][nf][2], acc[mf][nf][3],
                                aa[mf][0], aa[mf][1], aa[mf][2], aa[mf][3], bb[nf][0], bb[nf][1]);
            }
        }

        // Transposed epilogue: stage [n 128][c 64] halves (stride 72), write
        // g_qt[b][n][c] coalesced. Barrier first: smem still ring-resident.
        __syncthreads();
        __half* stg = (__half*)smu;
        #pragma unroll
        for (int mf = 0; mf < 2; mf++) {
            int cl = wm + mf * 16 + lr;
            #pragma unroll
            for (int nf = 0; nf < 4; nf++) {
                int nl = wn + nf * 8 + 2 * lc;
                #pragma unroll
                for (int h = 0; h < 2; h++) {
                    int c = cl + h * 8;
                    stg[(nl)     * 72 + c] = __float2half_rn(fmaxf(acc[mf][nf][2 * h],     0.0f));
                    stg[(nl + 1) * 72 + c] = __float2half_rn(fmaxf(acc[mf][nf][2 * h + 1], 0.0f));
                }
            }
        }
        __syncthreads();
        #pragma unroll
        for (int h = 0; h < 4; h++) {
            int idx = t + 256 * h;          // 0..1023 = 128 rows x 8 chunks
            int n = idx >> 3, c8 = idx & 7;
            uint4 d = *(uint4*)&stg[n * 72 + c8 * 8];
            *(uint4*)(g_qt + ((size_t)b * 1024 + n0 + n) * 128 + r0 + c8 * 8) = d;
        }
    }
}

// ---------------------------------------------------------------------------
// Causal attention, fp16 FA2-style (UNCHANGED from Round 10 pass):
//   - Q fragments register-resident from g_qt (32 u32)
//   - K [m][c] / V [c][m] half tiles, double-buffered, ONE barrier per iter
//   - warp-owned 16 q-rows x 64 keys (S) / x 128 v-channels (PV)
//   - softmax in registers; P half2 in warp-private smem strip
// ---------------------------------------------------------------------------
#define SKH 68
#define SVH 36
#define SPH 36
#define KS_U (64 * SKH)                 // 4352
#define VS_U (128 * SVH)                // 4608
#define A_KS0 0
#define A_KS1 KS_U
#define A_VS0 (2 * KS_U)
#define A_VS1 (2 * KS_U + VS_U)
#define A_PS  (2 * KS_U + 2 * VS_U)     // 17920
#define ATTN_SMEM_U (A_PS + 128 * SPH)  // 22528
#define ATTN_SMEM_BYTES (ATTN_SMEM_U * 4)

__global__ __launch_bounds__(256, 1) void attn_kernel(float* __restrict__ out)
{
    extern __shared__ uint32_t smu[];
    uint32_t* Ps = smu + A_PS;

    const int id = blockIdx.x;
    const int qt = 7 - (id >> 5);         // heavy q-tiles first (LPT)
    const int b = id & 31;
    const int n0 = qt * 128;
    const int mtMax = 2 * qt + 1;
    const int t = threadIdx.x, w = t >> 5, lane = t & 31;
    const int lr = lane >> 2, lc = lane & 3;
    const int wq = w * 16;
    const float scale = 0.08838834764831845f;
    const uint32_t sbase = (uint32_t)__cvta_generic_to_shared(smu);

    auto issue_stage = [&](int mt) {
        const int p = mt & 1;
        const int m0 = mt * 64;
        const uint32_t kb = sbase + (p ? A_KS1 : A_KS0) * 4;
        const uint32_t vb = sbase + (p ? A_VS1 : A_VS0) * 4;
        #pragma unroll
        for (int h = 0; h < 4; h++) {
            int idx = t + 256 * h;
            int m = idx >> 4, c16 = idx & 15;
            cpa16(kb + (m * SKH + c16 * 4) * 4,
                  g_kct + ((size_t)b * 1024 + m0 + m) * 128 + c16 * 8);
        }
        #pragma unroll
        for (int h = 0; h < 4; h++) {
            int idx = t + 256 * h;
            int c = idx >> 3, m16 = idx & 7;
            cpa16(vb + (c * SVH + m16 * 4) * 4,
                  g_vch + ((size_t)b * 128 + c) * 1024 + m0 + m16 * 8);
        }
        CP_COMMIT();
    };

    issue_stage(0);

    uint32_t qa[8][4];
    {
        const __half* qp = g_qt + ((size_t)b * 1024 + n0 + wq + lr) * 128;
        #pragma unroll
        for (int kf = 0; kf < 8; kf++) {
            qa[kf][0] = *(const uint32_t*)(qp + kf * 16 + 2 * lc);
            qa[kf][1] = *(const uint32_t*)(qp + 8 * 128 + kf * 16 + 2 * lc);
            qa[kf][2] = *(const uint32_t*)(qp + kf * 16 + 2 * lc + 8);
            qa[kf][3] = *(const uint32_t*)(qp + 8 * 128 + kf * 16 + 2 * lc + 8);
        }
    }

    float mLo = -1e30f, mHi = -1e30f, lLo = 0.0f, lHi = 0.0f;
    float O[16][4];
    #pragma unroll
    for (int nb = 0; nb < 16; nb++)
        #pragma unroll
        for (int jj = 0; jj < 4; jj++) O[nb][jj] = 0.0f;

    const int rowLo = n0 + wq + lr;
    const int rowHi = rowLo + 8;

    #pragma unroll 1
    for (int mt = 0; mt <= mtMax; mt++) {
        const int m0 = mt * 64;
        const uint32_t* Ks = smu + ((mt & 1) ? A_KS1 : A_KS0);
        const uint32_t* Vs = smu + ((mt & 1) ? A_VS1 : A_VS0);

        asm volatile("cp.async.wait_group 0;" ::: "memory");
        __syncthreads();
        if (mt < mtMax) issue_stage(mt + 1);

        float S[8][4];
        #pragma unroll
        for (int nb = 0; nb < 8; nb++)
            #pragma unroll
            for (int jj = 0; jj < 4; jj++) S[nb][jj] = 0.0f;

        #pragma unroll
        for (int kf = 0; kf < 8; kf++) {
            #pragma unroll
            for (int nb = 0; nb < 8; nb++) {
                int bbase = (nb * 8 + lr) * SKH + kf * 8 + lc;
                mma_f16(S[nb][0], S[nb][1], S[nb][2], S[nb][3],
                        qa[kf][0], qa[kf][1], qa[kf][2], qa[kf][3],
                        Ks[bbase], Ks[bbase + 4]);
            }
        }

        {
            const bool needMask = (m0 + 63 > n0 + wq);
            float tmLo = -1e30f, tmHi = -1e30f;
            #pragma unroll
            for (int nb = 0; nb < 8; nb++) {
                int c0 = m0 + nb * 8 + 2 * lc, c1 = c0 + 1;
                float s0 = S[nb][0] * scale, s1 = S[nb][1] * scale;
                float s2 = S[nb][2] * scale, s3 = S[nb][3] * scale;
                if (needMask) {
                    if (c0 > rowLo) s0 = -1e30f;
                    if (c1 > rowLo) s1 = -1e30f;
                    if (c0 > rowHi) s2 = -1e30f;
                    if (c1 > rowHi) s3 = -1e30f;
                }
                S[nb][0] = s0; S[nb][1] = s1; S[nb][2] = s2; S[nb][3] = s3;
                tmLo = fmaxf(tmLo, fmaxf(s0, s1));
                tmHi = fmaxf(tmHi, fmaxf(s2, s3));
            }
            tmLo = fmaxf(tmLo, __shfl_xor_sync(0xffffffffu, tmLo, 1));
            tmLo = fmaxf(tmLo, __shfl_xor_sync(0xffffffffu, tmLo, 2));
            tmHi = fmaxf(tmHi, __shfl_xor_sync(0xffffffffu, tmHi, 1));
            tmHi = fmaxf(tmHi, __shfl_xor_sync(0xffffffffu, tmHi, 2));
            float nmLo = fmaxf(mLo, tmLo), nmHi = fmaxf(mHi, tmHi);
            float aLo = __expf(mLo - nmLo), aHi = __expf(mHi - nmHi);
            mLo = nmLo; mHi = nmHi;
            float sLoSum = 0.0f, sHiSum = 0.0f;
            #pragma unroll
            for (int nb = 0; nb < 8; nb++) {
                float p0 = __expf(S[nb][0] - nmLo);
                float p1 = __expf(S[nb][1] - nmLo);
                float p2 = __expf(S[nb][2] - nmHi);
                float p3 = __expf(S[nb][3] - nmHi);
                sLoSum += p0 + p1;
                sHiSum += p2 + p3;
                Ps[(wq + lr) * SPH + nb * 4 + lc]     = h2u(__floats2half2_rn(p0, p1));
                Ps[(wq + lr + 8) * SPH + nb * 4 + lc] = h2u(__floats2half2_rn(p2, p3));
            }
            sLoSum += __shfl_xor_sync(0xffffffffu, sLoSum, 1);
            sLoSum += __shfl_xor_sync(0xffffffffu, sLoSum, 2);
            sHiSum += __shfl_xor_sync(0xffffffffu, sHiSum, 1);
            sHiSum += __shfl_xor_sync(0xffffffffu, sHiSum, 2);
            lLo = lLo * aLo + sLoSum;
            lHi = lHi * aHi + sHiSum;
            #pragma unroll
            for (int nb = 0; nb < 16; nb++) {
                O[nb][0] *= aLo; O[nb][1] *= aLo;
                O[nb][2] *= aHi; O[nb][3] *= aHi;
            }
        }
        __syncwarp();

        #pragma unroll
        for (int kf = 0; kf < 4; kf++) {
            int ab = (wq + lr) * SPH + kf * 8 + lc;
            uint32_t a0 = Ps[ab];
            uint32_t a1 = Ps[ab + 8 * SPH];
            uint32_t a2 = Ps[ab + 4];
            uint32_t a3 = Ps[ab + 8 * SPH + 4];
            #pragma unroll
            for (int nb = 0; nb < 16; nb++) {
                int bb = (nb * 8 + lr) * SVH + kf * 8 + lc;
                mma_f16(O[nb][0], O[nb][1], O[nb][2], O[nb][3],
                        a0, a1, a2, a3, Vs[bb], Vs[bb + 4]);
            }
        }
    }

    float iLo = 1.0f / lLo, iHi = 1.0f / lHi;
    #pragma unroll
    for (int nb = 0; nb < 16; nb++) {
        int vc = nb * 8 + 2 * lc;
        out[((size_t)(b * 128 + vc))     * 1024 + rowLo] = O[nb][0] * iLo;
        out[((size_t)(b * 128 + vc + 1)) * 1024 + rowLo] = O[nb][1] * iLo;
        out[((size_t)(b * 128 + vc))     * 1024 + rowHi] = O[nb][2] * iHi;
        out[((size_t)(b * 128 + vc + 1)) * 1024 + rowHi] = O[nb][3] * iHi;
    }
}

// ---------------------------------------------------------------------------
// Launch (single stream, graph-capturable)
// ---------------------------------------------------------------------------
extern "C" void kernel_launch(void* const* d_in, const int* in_sizes, int n_in,
                              void* d_out, int out_size)
{
    const float* x   = (const float*)d_in[0];
    const float* k   = (const float*)d_in[1];
    const float* v   = (const float*)d_in[2];
    const float* Wq  = (const float*)d_in[3];
    const float* bq  = (const float*)d_in[4];
    const float* Wfk = (const float*)d_in[5];
    const float* bfk = (const float*)d_in[6];
    const float* Wck = (const float*)d_in[7];
    const float* bck = (const float*)d_in[8];
    const float* Wfv = (const float*)d_in[9];
    const float* bfv = (const float*)d_in[10];
    const float* Wcv = (const float*)d_in[11];
    const float* bcv = (const float*)d_in[12];

    float* out2 = (float*)d_out;
    float* kn   = out2 + (size_t)32 * 128 * 1024;
    float* vn   = kn   + (size_t)32 * 128 * 1024;

    cudaFuncSetAttribute(fused_gemm_kernel, cudaFuncAttributeMaxDynamicSharedMemorySize, GSMEM_BYTES);
    cudaFuncSetAttribute(attn_kernel, cudaFuncAttributeMaxDynamicSharedMemorySize, ATTN_SMEM_BYTES);

    pos_kernel<<<32, 1024>>>();
    pack_kernel<<<PACK_BLOCKS, 256>>>(x, k, v, Wq, Wfk, Wck, Wfv, Wcv);
    fused_gemm_kernel<<<dim3(8, 2, 96), 256, GSMEM_BYTES>>>(
        k, v, bfk, bck, bfv, bcv, bq, kn, vn);
    attn_kernel<<<256, 256, ATTN_SMEM_BYTES>>>(out2);
}

// round 14
// speedup vs baseline: 1.8484x; 1.0170x over previous
#include <cuda_runtime.h>
#include <cuda_fp16.h>
#include <math.h>
#include <stdint.h>

// ---------------------------------------------------------------------------
// Scratch (__device__ globals; no allocation allowed)
// ---------------------------------------------------------------------------
__device__ float  g_pos[32 * 1024];               // [32 ch][1024 n], fp32
__device__ __half g_x0t[(size_t)32 * 1024 * 160]; // [b][n][c]  (x|pos), half
__device__ __half g_kct[(size_t)32 * 1024 * 128]; // [b][m][c]  k transposed
__device__ __half g_vct[(size_t)32 * 1024 * 128]; // [b][m][c]  v transposed
__device__ __half g_vch[(size_t)32 * 128 * 1024]; // [b][c][m]  v (orig orient, half)
__device__ __half g_qt [(size_t)32 * 1024 * 128]; // [b][n][c]  q transposed, PRE-SCALED
__device__ __half g_WqH [128 * 160];              // weights row-major half
__device__ __half g_WfkH[128 * 288];
__device__ __half g_WckH[128 * 288];
__device__ __half g_WfvH[128 * 288];
__device__ __half g_WcvH[128 * 288];

#define Q_SCALE 0.08838834764831845f

// ---------------------------------------------------------------------------
// Helpers
// ---------------------------------------------------------------------------
__device__ __forceinline__ void mma_f16(
    float& d0, float& d1, float& d2, float& d3,
    uint32_t a0, uint32_t a1, uint32_t a2, uint32_t a3,
    uint32_t b0, uint32_t b1)
{
    asm volatile(
        "mma.sync.aligned.m16n8k16.row.col.f32.f16.f16.f32 "
        "{%0,%1,%2,%3}, {%4,%5,%6,%7}, {%8,%9}, {%0,%1,%2,%3};"
        : "+f"(d0), "+f"(d1), "+f"(d2), "+f"(d3)
        : "r"(a0), "r"(a1), "r"(a2), "r"(a3), "r"(b0), "r"(b1));
}

__device__ __forceinline__ void cpa16(uint32_t dst, const void* src) {
    asm volatile("cp.async.ca.shared.global [%0], [%1], 16;" :: "r"(dst), "l"(src));
}
#define CP_COMMIT() asm volatile("cp.async.commit_group;" ::: "memory")

__device__ __forceinline__ uint32_t h2u(__half2 h) { return *(uint32_t*)&h; }

// ---------------------------------------------------------------------------
// Positional embedding (faithful to numpy .view reinterpret)
// ---------------------------------------------------------------------------
__global__ void pos_kernel() {
    int idx = blockIdx.x * blockDim.x + threadIdx.x;
    if (idx >= 32 * 1024) return;
    int c = idx >> 10, n = idx & 1023;
    int y = n >> 5, x = n & 31;
    int i = (c < 16) ? (c * 32 + y) : ((c - 16) * 32 + x);
    int p = i >> 4, j = i & 15;
    float r = 0.0f;
    if (p != 0) {
        double denom = pow(10000.0, (double)(2 * (j >> 1)) / 16.0);
        double val = (double)p / denom;
        r = (j & 1) ? (float)cos(val) : (float)sin(val);
    }
    g_pos[idx] = r;
}

// ---------------------------------------------------------------------------
// Pack kernel (R11 pass, unchanged)
// ---------------------------------------------------------------------------
#define PACK_BLOCKS 6738

__global__ void pack_kernel(const float* __restrict__ x,
                            const float* __restrict__ k,
                            const float* __restrict__ v,
                            const float* __restrict__ Wq,
                            const float* __restrict__ Wfk, const float* __restrict__ Wck,
                            const float* __restrict__ Wfv, const float* __restrict__ Wcv)
{
    __shared__ __half tile[64][40];
    const int j = blockIdx.x, t = threadIdx.x;

    if (j < 2560) {
        int b = j / 80, rem = j % 80, ct = rem / 16, m_t = rem % 16;
        int c0 = ct * 32, m0 = m_t * 64;
        #pragma unroll
        for (int e = 0; e < 8; e++) {
            int idx = t + 256 * e;
            int ci = idx >> 6, mj = idx & 63;
            int c = c0 + ci;
            float val = (c < 128)
                ? x[((size_t)b * 128 + c) * 1024 + m0 + mj]
                : g_pos[(c - 128) * 1024 + m0 + mj];
            tile[mj][ci] = __float2half_rn(val);
        }
        __syncthreads();
        int mj = t >> 2, c8 = t & 3;
        *(uint4*)(g_x0t + ((size_t)b * 1024 + m0 + mj) * 160 + c0 + c8 * 8) =
            *(uint4*)&tile[mj][c8 * 8];
    } else if (j < 6656) {
        int j2 = j - 2560;
        const bool isV = (j2 >= 2048);
        const float* src = isV ? v : k;
        __half* dst = isV ? g_vct : g_kct;
        j2 &= 2047;
        int b = j2 / 64, rem = j2 % 64, ct = rem / 16, m_t = rem % 16;
        int c0 = ct * 32, m0 = m_t * 64;
        #pragma unroll
        for (int e = 0; e < 8; e++) {
            int idx = t + 256 * e;
            int ci = idx >> 6, mj = idx & 63;
            __half h = __float2half_rn(src[((size_t)b * 128 + c0 + ci) * 1024 + m0 + mj]);
            tile[mj][ci] = h;
            if (isV)
                g_vch[((size_t)b * 128 + c0 + ci) * 1024 + m0 + mj] = h;
        }
        __syncthreads();
        int mj = t >> 2, c8 = t & 3;
        *(uint4*)(dst + ((size_t)b * 1024 + m0 + mj) * 128 + c0 + c8 * 8) =
            *(uint4*)&tile[mj][c8 * 8];
    } else {
        int j4 = j - 6656;
        int u0 = j4 * 2048 + t;
        #pragma unroll
        for (int i = 0; i < 8; i++) {
            int u = u0 + i * 256;
            if (u < 20480) {
                g_WqH[u] = __float2half_rn(Wq[u]);
            } else {
                int vv2 = u - 20480;
                int m = vv2 / 36864, o = vv2 % 36864;
                if (m == 0) g_WfkH[o] = __float2half_rn(Wfk[o]);
                else if (m == 1) g_WckH[o] = __float2half_rn(Wck[o]);
                else if (m == 2) g_WfvH[o] = __float2half_rn(Wfv[o]);
                else g_WcvH[o] = __float2half_rn(Wcv[o]);
            }
        }
    }
}

// ---------------------------------------------------------------------------
// Fused GEMM kernel (R11 pass; q epilogue now pre-scales by Q_SCALE)
// ---------------------------------------------------------------------------
#define ASH 20
#define BSH 20
#define GBUF_U 5120
#define QBUF_U 3840
#define GSMEM_BYTES (3 * GBUF_U * 4)

__global__ __launch_bounds__(256, 2) void fused_gemm_kernel(
    const float* __restrict__ kOrig, const float* __restrict__ vOrig,
    const float* __restrict__ bfk, const float* __restrict__ bck,
    const float* __restrict__ bfv, const float* __restrict__ bcv,
    const float* __restrict__ bq,
    float* __restrict__ outk, float* __restrict__ outv)
{
    extern __shared__ uint32_t smu[];
    const int r0 = blockIdx.y * 64, n0 = blockIdx.x * 128;
    const int t = threadIdx.x, w = t >> 5, lane = t & 31;
    const int lr = lane >> 2, lc = lane & 3;
    const int wm = (w >> 2) * 32;
    const int wn = (w & 3) * 32;
    const uint32_t sbase = (uint32_t)__cvta_generic_to_shared(smu);

    if (blockIdx.z < 64) {
        // ================= gated body =================
        const int z = blockIdx.z, b = z >> 1, which = z & 1;
        const __half* WfH = which ? g_WfvH : g_WfkH;
        const __half* WcH = which ? g_WcvH : g_WckH;
        const float* bfp = which ? bfv : bfk;
        const float* bcp = which ? bcv : bck;
        const __half* extcT = which ? g_vct : g_kct;
        const float* extra = which ? vOrig : kOrig;
        float* out = which ? outv : outk;

        float accF[2][4][4], accC[2][4][4];
        #pragma unroll
        for (int mf = 0; mf < 2; mf++) {
            int rA = r0 + wm + mf * 16 + lr;
            float bf0 = bfp[rA], bf1 = bfp[rA + 8];
            float bc0 = bcp[rA], bc1 = bcp[rA + 8];
            #pragma unroll
            for (int nf = 0; nf < 4; nf++) {
                accF[mf][nf][0] = bf0; accF[mf][nf][1] = bf0;
                accF[mf][nf][2] = bf1; accF[mf][nf][3] = bf1;
                accC[mf][nf][0] = bc0; accC[mf][nf][1] = bc0;
                accC[mf][nf][2] = bc1; accC[mf][nf][3] = bc1;
            }
        }

        auto issue = [&](int it, int buf) {
            const int k0 = it * 32;
            const uint32_t base = sbase + buf * (GBUF_U * 4);
            {
                int r = t >> 2, c4 = t & 3;
                cpa16(base + (r * ASH + c4 * 4) * 4,
                      WfH + (size_t)(r0 + r) * 288 + k0 + c4 * 8);
                cpa16(base + (1280 + r * ASH + c4 * 4) * 4,
                      WcH + (size_t)(r0 + r) * 288 + k0 + c4 * 8);
            }
            #pragma unroll
            for (int h = 0; h < 2; h++) {
                int idx = t + 256 * h;
                int r = idx >> 2, c4 = idx & 3;
                const __half* src = (k0 < 160)
                    ? (g_x0t + ((size_t)b * 1024 + n0 + r) * 160 + k0 + c4 * 8)
                    : (extcT + ((size_t)b * 1024 + n0 + r) * 128 + (k0 - 160) + c4 * 8);
                cpa16(base + (2560 + r * BSH + c4 * 4) * 4, src);
            }
            CP_COMMIT();
        };

        issue(0, 0);
        issue(1, 1);
        #pragma unroll 1
        for (int it = 0; it < 9; it++) {
            if (it < 8) {
                asm volatile("cp.async.wait_group 1;" ::: "memory");
            } else {
                asm volatile("cp.async.wait_group 0;" ::: "memory");
            }
            __syncthreads();
            if (it + 2 <= 8) issue(it + 2, (it + 2) % 3);

            const uint32_t* AsF = smu + (it % 3) * GBUF_U;
            const uint32_t* AsC = AsF + 1280;
            const uint32_t* Bs  = AsF + 2560;

            #pragma unroll
            for (int kf = 0; kf < 2; kf++) {
                uint32_t aF[2][4], aC[2][4], bb[4][2];
                #pragma unroll
                for (int mf = 0; mf < 2; mf++) {
                    int base = (wm + mf * 16 + lr) * ASH + kf * 8 + lc;
                    aF[mf][0] = AsF[base];
                    aF[mf][1] = AsF[base + 8 * ASH];
                    aF[mf][2] = AsF[base + 4];
                    aF[mf][3] = AsF[base + 8 * ASH + 4];
                    aC[mf][0] = AsC[base];
                    aC[mf][1] = AsC[base + 8 * ASH];
                    aC[mf][2] = AsC[base + 4];
                    aC[mf][3] = AsC[base + 8 * ASH + 4];
                }
                #pragma unroll
                for (int nf = 0; nf < 4; nf++) {
                    int base = (wn + nf * 8 + lr) * BSH + kf * 8 + lc;
                    bb[nf][0] = Bs[base];
                    bb[nf][1] = Bs[base + 4];
                }
                #pragma unroll
                for (int mf = 0; mf < 2; mf++)
                    #pragma unroll
                    for (int nf = 0; nf < 4; nf++) {
                        mma_f16(accF[mf][nf][0], accF[mf][nf][1], accF[mf][nf][2], accF[mf][nf][3],
                                aF[mf][0], aF[mf][1], aF[mf][2], aF[mf][3], bb[nf][0], bb[nf][1]);
                        mma_f16(accC[mf][nf][0], accC[mf][nf][1], accC[mf][nf][2], accC[mf][nf][3],
                                aC[mf][0], aC[mf][1], aC[mf][2], aC[mf][3], bb[nf][0], bb[nf][1]);
                    }
            }
        }

        #pragma unroll
        for (int mf = 0; mf < 2; mf++) {
            int rA = r0 + wm + mf * 16 + lr;
            #pragma unroll
            for (int nf = 0; nf < 4; nf++) {
                int n = n0 + wn + nf * 8 + 2 * lc;
                #pragma unroll
                for (int h = 0; h < 2; h++) {
                    int row = rA + h * 8;
                    #pragma unroll
                    for (int jj = 0; jj < 2; jj++) {
                        float F  = accF[mf][nf][2 * h + jj];
                        float Cc = accC[mf][nf][2 * h + jj];
                        float f  = 1.0f / (1.0f + __expf(-F));
                        float cc = fmaxf(Cc, 0.0f);
                        size_t off = ((size_t)(b * 128 + row)) * 1024 + n + jj;
                        out[off] = f * extra[off] + cc;
                    }
                }
            }
        }
    } else {
        // ================= q body =================
        const int b = blockIdx.z - 64;

        float acc[2][4][4];
        #pragma unroll
        for (int mf = 0; mf < 2; mf++) {
            int rA = r0 + wm + mf * 16 + lr;
            float b0 = bq[rA], b1 = bq[rA + 8];
            #pragma unroll
            for (int nf = 0; nf < 4; nf++) {
                acc[mf][nf][0] = b0; acc[mf][nf][1] = b0;
                acc[mf][nf][2] = b1; acc[mf][nf][3] = b1;
            }
        }

        auto issue = [&](int it, int buf) {
            const int k0 = it * 32;
            const uint32_t base = sbase + buf * (QBUF_U * 4);
            {
                int r = t >> 2, c4 = t & 3;
                cpa16(base + (r * ASH + c4 * 4) * 4,
                      g_WqH + (size_t)(r0 + r) * 160 + k0 + c4 * 8);
            }
            #pragma unroll
            for (int h = 0; h < 2; h++) {
                int idx = t + 256 * h;
                int r = idx >> 2, c4 = idx & 3;
                cpa16(base + (1280 + r * BSH + c4 * 4) * 4,
                      g_x0t + ((size_t)b * 1024 + n0 + r) * 160 + k0 + c4 * 8);
            }
            CP_COMMIT();
        };

        issue(0, 0);
        issue(1, 1);
        #pragma unroll 1
        for (int it = 0; it < 5; it++) {
            if (it < 4) {
                asm volatile("cp.async.wait_group 1;" ::: "memory");
            } else {
                asm volatile("cp.async.wait_group 0;" ::: "memory");
            }
            __syncthreads();
            if (it + 2 <= 4) issue(it + 2, (it + 2) % 3);

            const uint32_t* As = smu + (it % 3) * QBUF_U;
            const uint32_t* Bs = As + 1280;

            #pragma unroll
            for (int kf = 0; kf < 2; kf++) {
                uint32_t aa[2][4], bb[4][2];
                #pragma unroll
                for (int mf = 0; mf < 2; mf++) {
                    int base = (wm + mf * 16 + lr) * ASH + kf * 8 + lc;
                    aa[mf][0] = As[base];
                    aa[mf][1] = As[base + 8 * ASH];
                    aa[mf][2] = As[base + 4];
                    aa[mf][3] = As[base + 8 * ASH + 4];
                }
                #pragma unroll
                for (int nf = 0; nf < 4; nf++) {
                    int base = (wn + nf * 8 + lr) * BSH + kf * 8 + lc;
                    bb[nf][0] = Bs[base];
                    bb[nf][1] = Bs[base + 4];
                }
                #pragma unroll
                for (int mf = 0; mf < 2; mf++)
                    #pragma unroll
                    for (int nf = 0; nf < 4; nf++)
                        mma_f16(acc[mf][nf][0], acc[mf][nf][1], acc[mf][nf][2], acc[mf][nf][3],
                                aa[mf][0], aa[mf][1], aa[mf][2], aa[mf][3], bb[nf][0], bb[nf][1]);
            }
        }

        // Transposed epilogue, PRE-SCALED by Q_SCALE
        __syncthreads();
        __half* stg = (__half*)smu;
        #pragma unroll
        for (int mf = 0; mf < 2; mf++) {
            int cl = wm + mf * 16 + lr;
            #pragma unroll
            for (int nf = 0; nf < 4; nf++) {
                int nl = wn + nf * 8 + 2 * lc;
                #pragma unroll
                for (int h = 0; h < 2; h++) {
                    int c = cl + h * 8;
                    stg[(nl)     * 72 + c] =
                        __float2half_rn(fmaxf(acc[mf][nf][2 * h],     0.0f) * Q_SCALE);
                    stg[(nl + 1) * 72 + c] =
                        __float2half_rn(fmaxf(acc[mf][nf][2 * h + 1], 0.0f) * Q_SCALE);
                }
            }
        }
        __syncthreads();
        #pragma unroll
        for (int h = 0; h < 4; h++) {
            int idx = t + 256 * h;
            int n = idx >> 3, c8 = idx & 7;
            uint4 d = *(uint4*)&stg[n * 72 + c8 * 8];
            *(uint4*)(g_qt + ((size_t)b * 1024 + n0 + n) * 128 + r0 + c8 * 8) = d;
        }
    }
}

// ---------------------------------------------------------------------------
// Causal attention, fp16 FA2-style, Round 14:
//   64-query CTAs, 128 threads (4 warps), 512 CTAs -> 2 CTAs/SM co-resident.
//   Same warp tile (16 q-rows x 64 keys S / x 128 v-ch PV), double-buffered
//   K/V with ONE barrier per iteration; softmax in regs; q pre-scaled.
// smem: 2*K(64x68) + 2*V(128x36) + Ps(64x36) = 20224 u32 = 80896 B; x2/SM.
// ---------------------------------------------------------------------------
#define SKH 68
#define SVH 36
#define SPH 36
#define KS_U (64 * SKH)                 // 4352
#define VS_U (128 * SVH)                // 4608
#define A_KS0 0
#define A_KS1 KS_U
#define A_VS0 (2 * KS_U)
#define A_VS1 (2 * KS_U + VS_U)
#define A_PS  (2 * KS_U + 2 * VS_U)     // 17920
#define ATTN_SMEM_U (A_PS + 64 * SPH)   // 20224
#define ATTN_SMEM_BYTES (ATTN_SMEM_U * 4)

__global__ __launch_bounds__(128, 2) void attn_kernel(float* __restrict__ out)
{
    extern __shared__ uint32_t smu[];
    uint32_t* Ps = smu + A_PS;

    const int id = blockIdx.x;
    const int qt = 15 - (id >> 5);        // heavy q-tiles first (LPT)
    const int b = id & 31;
    const int n0 = qt * 64;
    const int mtMax = qt;
    const int t = threadIdx.x, w = t >> 5, lane = t & 31;
    const int lr = lane >> 2, lc = lane & 3;
    const int wq = w * 16;                // 0,16,32,48
    const uint32_t sbase = (uint32_t)__cvta_generic_to_shared(smu);

    auto issue_stage = [&](int mt) {
        const int p = mt & 1;
        const int m0 = mt * 64;
        const uint32_t kb = sbase + (p ? A_KS1 : A_KS0) * 4;
        const uint32_t vb = sbase + (p ? A_VS1 : A_VS0) * 4;
        #pragma unroll
        for (int h = 0; h < 8; h++) {     // K: 64 rows x 16 chunks
            int idx = t + 128 * h;
            int m = idx >> 4, c16 = idx & 15;
            cpa16(kb + (m * SKH + c16 * 4) * 4,
                  g_kct + ((size_t)b * 1024 + m0 + m) * 128 + c16 * 8);
        }
        #pragma unroll
        for (int h = 0; h < 8; h++) {     // V: 128 rows x 8 chunks
            int idx = t + 128 * h;
            int c = idx >> 3, m16 = idx & 7;
            cpa16(vb + (c * SVH + m16 * 4) * 4,
                  g_vch + ((size_t)b * 128 + c) * 1024 + m0 + m16 * 8);
        }
        CP_COMMIT();
    };

    issue_stage(0);

    // Q fragments register-resident (q already scaled by 1/sqrt(128))
    uint32_t qa[8][4];
    {
        const __half* qp = g_qt + ((size_t)b * 1024 + n0 + wq + lr) * 128;
        #pragma unroll
        for (int kf = 0; kf < 8; kf++) {
            qa[kf][0] = *(const uint32_t*)(qp + kf * 16 + 2 * lc);
            qa[kf][1] = *(const uint32_t*)(qp + 8 * 128 + kf * 16 + 2 * lc);
            qa[kf][2] = *(const uint32_t*)(qp + kf * 16 + 2 * lc + 8);
            qa[kf][3] = *(const uint32_t*)(qp + 8 * 128 + kf * 16 + 2 * lc + 8);
        }
    }

    float mLo = -1e30f, mHi = -1e30f, lLo = 0.0f, lHi = 0.0f;
    float O[16][4];
    #pragma unroll
    for (int nb = 0; nb < 16; nb++)
        #pragma unroll
        for (int jj = 0; jj < 4; jj++) O[nb][jj] = 0.0f;

    const int rowLo = n0 + wq + lr;
    const int rowHi = rowLo + 8;

    #pragma unroll 1
    for (int mt = 0; mt <= mtMax; mt++) {
        const int m0 = mt * 64;
        const uint32_t* Ks = smu + ((mt & 1) ? A_KS1 : A_KS0);
        const uint32_t* Vs = smu + ((mt & 1) ? A_VS1 : A_VS0);

        asm volatile("cp.async.wait_group 0;" ::: "memory");
        __syncthreads();
        if (mt < mtMax) issue_stage(mt + 1);

        // ---- S = Q K^T : warp tile 16 x 64 ----
        float S[8][4];
        #pragma unroll
        for (int nb = 0; nb < 8; nb++)
            #pragma unroll
            for (int jj = 0; jj < 4; jj++) S[nb][jj] = 0.0f;

        #pragma unroll
        for (int kf = 0; kf < 8; kf++) {
            #pragma unroll
            for (int nb = 0; nb < 8; nb++) {
                int bbase = (nb * 8 + lr) * SKH + kf * 8 + lc;
                mma_f16(S[nb][0], S[nb][1], S[nb][2], S[nb][3],
                        qa[kf][0], qa[kf][1], qa[kf][2], qa[kf][3],
                        Ks[bbase], Ks[bbase + 4]);
            }
        }

        // ---- In-register online softmax (warp-local) ----
        {
            const bool needMask = (m0 + 63 > n0 + wq);
            float tmLo = -1e30f, tmHi = -1e30f;
            #pragma unroll
            for (int nb = 0; nb < 8; nb++) {
                int c0 = m0 + nb * 8 + 2 * lc, c1 = c0 + 1;
                float s0 = S[nb][0], s1 = S[nb][1];
                float s2 = S[nb][2], s3 = S[nb][3];
                if (needMask) {
                    if (c0 > rowLo) s0 = -1e30f;
                    if (c1 > rowLo) s1 = -1e30f;
                    if (c0 > rowHi) s2 = -1e30f;
                    if (c1 > rowHi) s3 = -1e30f;
                }
                S[nb][0] = s0; S[nb][1] = s1; S[nb][2] = s2; S[nb][3] = s3;
                tmLo = fmaxf(tmLo, fmaxf(s0, s1));
                tmHi = fmaxf(tmHi, fmaxf(s2, s3));
            }
            tmLo = fmaxf(tmLo, __shfl_xor_sync(0xffffffffu, tmLo, 1));
            tmLo = fmaxf(tmLo, __shfl_xor_sync(0xffffffffu, tmLo, 2));
            tmHi = fmaxf(tmHi, __shfl_xor_sync(0xffffffffu, tmHi, 1));
            tmHi = fmaxf(tmHi, __shfl_xor_sync(0xffffffffu, tmHi, 2));
            float nmLo = fmaxf(mLo, tmLo), nmHi = fmaxf(mHi, tmHi);
            float aLo = __expf(mLo - nmLo), aHi = __expf(mHi - nmHi);
            mLo = nmLo; mHi = nmHi;
            float sLoSum = 0.0f, sHiSum = 0.0f;
            #pragma unroll
            for (int nb = 0; nb < 8; nb++) {
                float p0 = __expf(S[nb][0] - nmLo);
                float p1 = __expf(S[nb][1] - nmLo);
                float p2 = __expf(S[nb][2] - nmHi);
                float p3 = __expf(S[nb][3] - nmHi);
                sLoSum += p0 + p1;
                sHiSum += p2 + p3;
                Ps[(wq + lr) * SPH + nb * 4 + lc]     = h2u(__floats2half2_rn(p0, p1));
                Ps[(wq + lr + 8) * SPH + nb * 4 + lc] = h2u(__floats2half2_rn(p2, p3));
            }
            sLoSum += __shfl_xor_sync(0xffffffffu, sLoSum, 1);
            sLoSum += __shfl_xor_sync(0xffffffffu, sLoSum, 2);
            sHiSum += __shfl_xor_sync(0xffffffffu, sHiSum, 1);
            sHiSum += __shfl_xor_sync(0xffffffffu, sHiSum, 2);
            lLo = lLo * aLo + sLoSum;
            lHi = lHi * aHi + sHiSum;
            #pragma unroll
            for (int nb = 0; nb < 16; nb++) {
                O[nb][0] *= aLo; O[nb][1] *= aLo;
                O[nb][2] *= aHi; O[nb][3] *= aHi;
            }
        }
        __syncwarp();   // Ps strip is warp-private

        // ---- O += P V^T : 16 rows x 128 v-channels ----
        #pragma unroll
        for (int kf = 0; kf < 4; kf++) {
            int ab = (wq + lr) * SPH + kf * 8 + lc;
            uint32_t a0 = Ps[ab];
            uint32_t a1 = Ps[ab + 8 * SPH];
            uint32_t a2 = Ps[ab + 4];
            uint32_t a3 = Ps[ab + 8 * SPH + 4];
            #pragma unroll
            for (int nb = 0; nb < 16; nb++) {
                int bb = (nb * 8 + lr) * SVH + kf * 8 + lc;
                mma_f16(O[nb][0], O[nb][1], O[nb][2], O[nb][3],
                        a0, a1, a2, a3, Vs[bb], Vs[bb + 4]);
            }
        }
    }

    float iLo = 1.0f / lLo, iHi = 1.0f / lHi;
    #pragma unroll
    for (int nb = 0; nb < 16; nb++) {
        int vc = nb * 8 + 2 * lc;
        out[((size_t)(b * 128 + vc))     * 1024 + rowLo] = O[nb][0] * iLo;
        out[((size_t)(b * 128 + vc + 1)) * 1024 + rowLo] = O[nb][1] * iLo;
        out[((size_t)(b * 128 + vc))     * 1024 + rowHi] = O[nb][2] * iHi;
        out[((size_t)(b * 128 + vc + 1)) * 1024 + rowHi] = O[nb][3] * iHi;
    }
}

// ---------------------------------------------------------------------------
// Launch (single stream, graph-capturable)
// ---------------------------------------------------------------------------
extern "C" void kernel_launch(void* const* d_in, const int* in_sizes, int n_in,
                              void* d_out, int out_size)
{
    const float* x   = (const float*)d_in[0];
    const float* k   = (const float*)d_in[1];
    const float* v   = (const float*)d_in[2];
    const float* Wq  = (const float*)d_in[3];
    const float* bq  = (const float*)d_in[4];
    const float* Wfk = (const float*)d_in[5];
    const float* bfk = (const float*)d_in[6];
    const float* Wck = (const float*)d_in[7];
    const float* bck = (const float*)d_in[8];
    const float* Wfv = (const float*)d_in[9];
    const float* bfv = (const float*)d_in[10];
    const float* Wcv = (const float*)d_in[11];
    const float* bcv = (const float*)d_in[12];

    float* out2 = (float*)d_out;
    float* kn   = out2 + (size_t)32 * 128 * 1024;
    float* vn   = kn   + (size_t)32 * 128 * 1024;

    cudaFuncSetAttribute(fused_gemm_kernel, cudaFuncAttributeMaxDynamicSharedMemorySize, GSMEM_BYTES);
    cudaFuncSetAttribute(attn_kernel, cudaFuncAttributeMaxDynamicSharedMemorySize, ATTN_SMEM_BYTES);

    pos_kernel<<<32, 1024>>>();
    pack_kernel<<<PACK_BLOCKS, 256>>>(x, k, v, Wq, Wfk, Wck, Wfv, Wcv);
    fused_gemm_kernel<<<dim3(8, 2, 96), 256, GSMEM_BYTES>>>(
        k, v, bfk, bck, bfv, bcv, bq, kn, vn);
    attn_kernel<<<512, 128, ATTN_SMEM_BYTES>>>(out2);
}